// round 12
// baseline (speedup 1.0000x reference)
#include <cuda_runtime.h>
#include <cuda_fp16.h>
#include <cstdint>

// GAU block on GB300 (plain sm_103 target): fp16 1-pass GEMMs on
// mma.sync.m16n8k16 + ldmatrix + cp.async.
// R12 = R11 with capture-legal stream fork order (s1 forked from stream 0
// BEFORE any s1 launch). Persistent 296-CTA V GEMM; split converters.
// B=4, S=2048, D=512, QKD=256, HID=1536

constexpr int Bn = 4, Sn = 2048, Dn = 512, QKDn = 256, HIDn = 1536;
constexpr int BSn = Bn * Sn;                 // 8192
constexpr float LN_EPS = 1e-5f;

// ----------------------------------------------------------------------------
// scratch (device globals)
// ----------------------------------------------------------------------------
static __device__ __align__(16) __half g_xh[BSn * Dn];
static __device__ __align__(16) __half g_Wmh[Dn * Dn];
static __device__ __align__(16) __half g_Whh[2 * HIDn * Dn];
static __device__ __align__(16) __half g_Wqh[QKDn * Dn];
static __device__ __align__(16) __half g_Woh[Dn * HIDn];
static __device__ __align__(16) __half g_WbTh[QKDn * QKDn];
static __device__ __align__(16) float  g_tmp1[BSn * Dn];
static __device__ __align__(16) __half g_nh[BSn * Dn];
static __device__ __align__(16) __half g_hbuf[BSn * 2 * HIDn];          // [v | gate]
static __device__ __align__(16) __half g_Zh[BSn * QKDn];
static __device__ __align__(16) __half g_ZWh[BSn * QKDn];
static __device__ __align__(16) __half g_Amh[(long long)Bn * Sn * Sn];
static __device__ __align__(16) __half g_Vh[BSn * HIDn];
static __device__ __align__(16) float  g_U[BSn * Dn];

// ----------------------------------------------------------------------------
// PTX helpers
// ----------------------------------------------------------------------------
__device__ __forceinline__ uint32_t smem_u32(const void* p) {
    uint32_t a;
    asm("{ .reg .u64 t; cvta.to.shared.u64 t, %1; cvt.u32.u64 %0, t; }"
        : "=r"(a) : "l"(p));
    return a;
}
__device__ __forceinline__ void cpa16(uint32_t saddr, const void* gaddr) {
    asm volatile("cp.async.cg.shared.global [%0], [%1], 16;"
                 :: "r"(saddr), "l"(gaddr) : "memory");
}
__device__ __forceinline__ void cpa_commit() {
    asm volatile("cp.async.commit_group;" ::: "memory");
}
template<int N>
__device__ __forceinline__ void cpa_wait() {
    asm volatile("cp.async.wait_group %0;" :: "n"(N) : "memory");
}
__device__ __forceinline__ void ldm_x4(uint32_t a, uint32_t& r0, uint32_t& r1,
                                       uint32_t& r2, uint32_t& r3) {
    asm volatile("ldmatrix.sync.aligned.m8n8.x4.shared.b16 {%0,%1,%2,%3}, [%4];"
                 : "=r"(r0), "=r"(r1), "=r"(r2), "=r"(r3) : "r"(a));
}
__device__ __forceinline__ void ldm_x4_trans(uint32_t a, uint32_t& r0, uint32_t& r1,
                                             uint32_t& r2, uint32_t& r3) {
    asm volatile("ldmatrix.sync.aligned.m8n8.x4.trans.shared.b16 {%0,%1,%2,%3}, [%4];"
                 : "=r"(r0), "=r"(r1), "=r"(r2), "=r"(r3) : "r"(a));
}
__device__ __forceinline__ void mma_f16(float* c, const uint32_t* a, uint32_t b0, uint32_t b1) {
    asm volatile(
        "mma.sync.aligned.m16n8k16.row.col.f32.f16.f16.f32 "
        "{%0,%1,%2,%3}, {%4,%5,%6,%7}, {%8,%9}, {%0,%1,%2,%3};"
        : "+f"(c[0]), "+f"(c[1]), "+f"(c[2]), "+f"(c[3])
        : "r"(a[0]), "r"(a[1]), "r"(a[2]), "r"(a[3]), "r"(b0), "r"(b1));
}
__device__ __forceinline__ uint32_t pack2(__half a, __half b) {
    return (uint32_t)__half_as_ushort(a) | ((uint32_t)__half_as_ushort(b) << 16);
}

// ----------------------------------------------------------------------------
// tensor GEMM (1-pass): C[m,n] = sum_k A[m,k]*B[n,k]
// Grid-stride tile loop (launch grid <= tilesX*tilesY*tilesZ).
// A K-major. B: TRB==false -> K-major; TRB==true -> N-major (ldmatrix.trans).
// CTA tile 128x128, K-tile 32, 4 warps (2x2, 64x64 warp tiles), 3-stage pipe.
// OUT: 0 = fp32, 1 = fp16.  EPI_GATE extra fp16, EPI_BIAS_ADDX extra fp32.
// ----------------------------------------------------------------------------
enum { EPI_NONE = 0, EPI_BIAS = 1, EPI_BIAS_RELU = 2, EPI_BIAS_ADDX = 3,
       EPI_RELUSQ = 4, EPI_GATE = 5 };

constexpr int TROW = 80;
constexpr int TILE_B = 128 * TROW;             // 10240
constexpr int TRB_ROW = 272;
constexpr int TRB_TILE = 32 * TRB_ROW;         // 8704
template<bool TRB> struct StageCfg {
    static constexpr int STAGE_B = TILE_B + (TRB ? TRB_TILE : TILE_B);
    static constexpr int SMEM = 3 * STAGE_B;
};

__device__ __forceinline__ void fill_tile(uint32_t sbase,
                                          const __half* __restrict__ g,
                                          long long row0, int ld, long long k0, int tid)
{
    #pragma unroll
    for (int it = 0; it < 4; ++it) {
        int q = tid + it * 128;
        int r = q >> 2, c = q & 3;
        cpa16(sbase + r * TROW + c * 16,
              g + (row0 + r) * (long long)ld + k0 + c * 8);
    }
}

__device__ __forceinline__ void fill_tile_trb(uint32_t sbase,
                                              const __half* __restrict__ g,
                                              long long n0, int ld, long long k0, int tid)
{
    #pragma unroll
    for (int it = 0; it < 4; ++it) {
        int q = tid + it * 128;
        int r = q >> 4, c = q & 15;
        cpa16(sbase + r * TRB_ROW + c * 16,
              g + (k0 + r) * (long long)ld + n0 + c * 8);
    }
}

template<int EPI, int OUT, bool TRB = false>
__global__ void __launch_bounds__(128, 2)
tgemm(const __half* __restrict__ pA,
      const __half* __restrict__ pB,
      const float* __restrict__ bias, const void* __restrict__ extra,
      float* __restrict__ Cf, __half* __restrict__ Ch,
      int K, int lda, int ldb, int ldc,
      long long sA, long long sB, long long sC, long long sE,
      int lde, float scale,
      int tilesX, int tilesY, int tilesZ)
{
    constexpr int STAGE_B = StageCfg<TRB>::STAGE_B;
    extern __shared__ char smem[];
    const int tid = threadIdx.x;
    const int wid = tid >> 5, lane = tid & 31;
    const uint32_t sb = smem_u32(smem);

    const int wm = (wid >> 1) * 64;
    const int wn = (wid & 1) * 64;
    const int rowL = (lane & 7) + ((lane >> 3) & 1) * 8;
    const int cOff = lane >> 4;
    const int rql = lane >> 2;
    const int cql = (lane & 3) * 2;
    const int KT = K >> 5;
    const int total = tilesX * tilesY * tilesZ;

    for (int t = blockIdx.x; t < total; t += gridDim.x) {
        const int nx = t % tilesX;
        const int rm = t / tilesX;
        const int my = rm % tilesY;
        const int z  = rm / tilesY;

        const __half* A = pA + (long long)z * sA;
        const __half* B = pB + (long long)z * sB;
        const float*  Exf = (EPI == EPI_BIAS_ADDX && extra)
                            ? (const float*)extra + (long long)z * sE : nullptr;
        const __half* Exh = (EPI == EPI_GATE && extra)
                            ? (const __half*)extra + (long long)z * sE : nullptr;
        const long long coff = (long long)z * sC;
        const long long m0 = (long long)my * 128;
        const long long n0 = (long long)nx * 128;

        float acc[4][8][4];
        #pragma unroll
        for (int i = 0; i < 4; ++i)
            #pragma unroll
            for (int j = 0; j < 8; ++j)
                #pragma unroll
                for (int q = 0; q < 4; ++q) acc[i][j][q] = 0.0f;

        auto fill_stage = [&](int stage, long long k0) {
            uint32_t s = sb + stage * STAGE_B;
            fill_tile(s, A, m0, lda, k0, tid);
            if (TRB) fill_tile_trb(s + TILE_B, B, n0, ldb, k0, tid);
            else     fill_tile(s + TILE_B, B, n0, ldb, k0, tid);
        };

        #pragma unroll
        for (int s = 0; s < 2; ++s) {
            fill_stage(s, (long long)s * 32);
            cpa_commit();
        }

        for (int kt = 0; kt < KT; ++kt) {
            const int fs = kt + 2;
            if (fs < KT) fill_stage(fs % 3, (long long)fs * 32);
            cpa_commit();
            cpa_wait<2>();
            __syncthreads();

            const uint32_t st = sb + (kt % 3) * STAGE_B;
            const uint32_t aB = st;
            const uint32_t bB = st + TILE_B;

            #pragma unroll
            for (int kk = 0; kk < 2; ++kk) {
                const int cc = kk * 2 + cOff;
                uint32_t ah[4][4];
                #pragma unroll
                for (int im = 0; im < 4; ++im) {
                    uint32_t off = (uint32_t)((wm + im * 16 + rowL) * TROW + cc * 16);
                    ldm_x4(aB + off, ah[im][0], ah[im][1], ah[im][2], ah[im][3]);
                }
                uint32_t bh[4][4];
                #pragma unroll
                for (int nb = 0; nb < 4; ++nb) {
                    if (TRB) {
                        uint32_t off = (uint32_t)(
                            (kk * 16 + ((lane >> 4) & 1) * 8 + (lane & 7)) * TRB_ROW +
                            (wn + nb * 16 + ((lane >> 3) & 1) * 8) * 2);
                        ldm_x4_trans(bB + off, bh[nb][0], bh[nb][1], bh[nb][2], bh[nb][3]);
                    } else {
                        uint32_t off = (uint32_t)((wn + nb * 16 + rowL) * TROW + cc * 16);
                        ldm_x4(bB + off, bh[nb][0], bh[nb][1], bh[nb][2], bh[nb][3]);
                    }
                }
                #pragma unroll
                for (int im = 0; im < 4; ++im) {
                    #pragma unroll
                    for (int j = 0; j < 8; ++j) {
                        const int nb = j >> 1, sel = j & 1;
                        mma_f16(acc[im][j], ah[im], bh[nb][sel], bh[nb][sel + 2]);
                    }
                }
            }
            __syncthreads();
        }

        // ---- epilogue ----
        #pragma unroll
        for (int im = 0; im < 4; ++im) {
            #pragma unroll
            for (int j = 0; j < 8; ++j) {
                #pragma unroll
                for (int half = 0; half < 2; ++half) {
                    const long long gm = m0 + wm + im * 16 + rql + half * 8;
                    const long long gn = n0 + wn + j * 8 + cql;
                    float v0 = acc[im][j][half * 2 + 0];
                    float v1 = acc[im][j][half * 2 + 1];

                    if (EPI == EPI_BIAS || EPI == EPI_BIAS_RELU || EPI == EPI_BIAS_ADDX) {
                        float2 bv = *reinterpret_cast<const float2*>(&bias[gn]);
                        v0 += bv.x; v1 += bv.y;
                    }
                    if (EPI == EPI_BIAS_RELU) { v0 = fmaxf(v0, 0.0f); v1 = fmaxf(v1, 0.0f); }
                    if (EPI == EPI_BIAS_ADDX) {
                        float2 ev = *reinterpret_cast<const float2*>(&Exf[gm * lde + gn]);
                        v0 += ev.x; v1 += ev.y;
                    }
                    if (EPI == EPI_GATE) {
                        uint32_t gp = *reinterpret_cast<const uint32_t*>(&Exh[gm * lde + gn]);
                        v0 *= __half2float(__ushort_as_half((unsigned short)(gp & 0xFFFF)));
                        v1 *= __half2float(__ushort_as_half((unsigned short)(gp >> 16)));
                    }
                    if (EPI == EPI_RELUSQ) {
                        float r0 = fmaxf(v0 * scale, 0.0f), r1 = fmaxf(v1 * scale, 0.0f);
                        v0 = r0 * r0; v1 = r1 * r1;
                    }

                    const long long oi = coff + gm * ldc + gn;
                    if (OUT == 0) {
                        *reinterpret_cast<float2*>(&Cf[oi]) = make_float2(v0, v1);
                    } else {
                        *reinterpret_cast<uint32_t*>(&Ch[oi]) =
                            pack2(__float2half_rn(v0), __float2half_rn(v1));
                    }
                }
            }
        }
    }
}

// ----------------------------------------------------------------------------
// LayerNorm (D=512)
// ----------------------------------------------------------------------------
__device__ __forceinline__ float block_sum_512(float v, float* red)
{
    #pragma unroll
    for (int o = 16; o > 0; o >>= 1) v += __shfl_down_sync(0xffffffffu, v, o);
    if ((threadIdx.x & 31) == 0) red[threadIdx.x >> 5] = v;
    __syncthreads();
    if (threadIdx.x == 0) {
        float s = 0.0f;
        #pragma unroll
        for (int i = 0; i < 8; i++) s += red[i];
        red[0] = s;
    }
    __syncthreads();
    float r = red[0];
    __syncthreads();
    return r;
}

template<bool HALF_OUT>
__global__ void __launch_bounds__(256)
ln_kernel(const float* __restrict__ in, const float* __restrict__ g,
          const float* __restrict__ b, const float* __restrict__ resid,
          float* __restrict__ outf, __half* __restrict__ oh)
{
    __shared__ float red[8];
    const long long row = blockIdx.x;
    const int t = threadIdx.x;
    const float* rp = in + row * Dn;

    float v0 = rp[t], v1 = rp[t + 256];
    float mean = block_sum_512(v0 + v1, red) * (1.0f / Dn);
    float d0 = v0 - mean, d1 = v1 - mean;
    float var = block_sum_512(d0 * d0 + d1 * d1, red) * (1.0f / Dn);
    float inv = rsqrtf(var + LN_EPS);

    float o0 = d0 * inv * g[t]       + b[t];
    float o1 = d1 * inv * g[t + 256] + b[t + 256];
    if (HALF_OUT) {
        oh[row * Dn + t]       = __float2half_rn(o0);
        oh[row * Dn + t + 256] = __float2half_rn(o1);
    } else {
        if (resid) {
            o0 += resid[row * Dn + t];
            o1 += resid[row * Dn + t + 256];
        }
        outf[row * Dn + t]       = o0;
        outf[row * Dn + t + 256] = o1;
    }
}

// ----------------------------------------------------------------------------
// converters
// ----------------------------------------------------------------------------
constexpr int Q_X  = BSn * Dn / 4;
constexpr int Q_WM = Dn * Dn / 4;
constexpr int Q_WH = 2 * HIDn * Dn / 4;
constexpr int Q_WQ = QKDn * Dn / 4;
constexpr int Q_WO = Dn * HIDn / 4;
constexpr int Q_XM   = Q_X + Q_WM;
constexpr int Q_REST = Q_WH + Q_WQ + Q_WO;

__global__ void __launch_bounds__(256)
cvt_xm_kernel(const float* __restrict__ x,  __half* xh,
              const float* __restrict__ wm, __half* wmh)
{
    int i = blockIdx.x * 256 + threadIdx.x;
    if (i >= Q_XM) return;
    const float* in; __half* oh;
    if (i < Q_X) { in = x; oh = xh; }
    else         { i -= Q_X; in = wm; oh = wmh; }
    float4 v = reinterpret_cast<const float4*>(in)[i];
    reinterpret_cast<uint2*>(oh)[i] = make_uint2(
        pack2(__float2half_rn(v.x), __float2half_rn(v.y)),
        pack2(__float2half_rn(v.z), __float2half_rn(v.w)));
}

__global__ void __launch_bounds__(256)
cvt_rest_kernel(const float* __restrict__ wh, __half* whh,
                const float* __restrict__ wq, __half* wqh,
                const float* __restrict__ wo, __half* woh)
{
    int i = blockIdx.x * 256 + threadIdx.x;
    if (i >= Q_REST) return;
    const float* in; __half* oh;
    if (i < Q_WH)                { in = wh; oh = whh; }
    else if ((i -= Q_WH) < Q_WQ) { in = wq; oh = wqh; }
    else     { i -= Q_WQ;          in = wo; oh = woh; }
    float4 v = reinterpret_cast<const float4*>(in)[i];
    reinterpret_cast<uint2*>(oh)[i] = make_uint2(
        pack2(__float2half_rn(v.x), __float2half_rn(v.y)),
        pack2(__float2half_rn(v.z), __float2half_rn(v.w)));
}

// transpose (fp32 in, fp16 out): out[c][r] = in[r][c]   (Wb only)
__global__ void __launch_bounds__(256)
cvt_tr_kernel(const float* __restrict__ in, __half* __restrict__ oh,
              int ldin, int ldout)
{
    __shared__ float tbuf[32][33];
    const int c0 = blockIdx.x * 32, r0 = blockIdx.y * 32;
    const int tx = threadIdx.x & 31, ty = threadIdx.x >> 5;

    #pragma unroll
    for (int i = 0; i < 4; i++)
        tbuf[ty + i * 8][tx] = in[(long long)(r0 + ty + i * 8) * ldin + c0 + tx];
    __syncthreads();
    #pragma unroll
    for (int i = 0; i < 4; i++) {
        float v = tbuf[tx][ty + i * 8];
        long long oi = (long long)(c0 + ty + i * 8) * ldout + r0 + tx;
        oh[oi] = __float2half_rn(v);
    }
}

// ----------------------------------------------------------------------------
// launch
// ----------------------------------------------------------------------------
extern "C" void kernel_launch(void* const* d_in, const int* in_sizes, int n_in,
                              void* d_out, int out_size)
{
    const float* x  = (const float*)d_in[0];
    const float* Wm = (const float*)d_in[1];
    const float* bm = (const float*)d_in[2];
    const float* g1 = (const float*)d_in[3];
    const float* b1 = (const float*)d_in[4];
    const float* Wh = (const float*)d_in[5];
    const float* bh = (const float*)d_in[6];
    const float* Wq = (const float*)d_in[7];
    const float* bq = (const float*)d_in[8];
    const float* Wb = (const float*)d_in[9];
    const float* Wo = (const float*)d_in[10];
    const float* bo = (const float*)d_in[11];
    const float* g2 = (const float*)d_in[12];
    const float* b2 = (const float*)d_in[13];
    float* out = (float*)d_out;

    __half *xh, *Wmh, *Whh, *Wqh, *Woh, *WbTh;
    __half *nh, *Zh, *ZWh, *Amh, *Vh, *hb;
    float *tmp1, *U;
    cudaGetSymbolAddress((void**)&xh, g_xh);
    cudaGetSymbolAddress((void**)&Wmh, g_Wmh);
    cudaGetSymbolAddress((void**)&Whh, g_Whh);
    cudaGetSymbolAddress((void**)&Wqh, g_Wqh);
    cudaGetSymbolAddress((void**)&Woh, g_Woh);
    cudaGetSymbolAddress((void**)&WbTh, g_WbTh);
    cudaGetSymbolAddress((void**)&nh, g_nh);
    cudaGetSymbolAddress((void**)&Zh, g_Zh);
    cudaGetSymbolAddress((void**)&ZWh, g_ZWh);
    cudaGetSymbolAddress((void**)&Amh, g_Amh);
    cudaGetSymbolAddress((void**)&Vh, g_Vh);
    cudaGetSymbolAddress((void**)&hb, g_hbuf);
    cudaGetSymbolAddress((void**)&tmp1, g_tmp1);
    cudaGetSymbolAddress((void**)&U, g_U);

    constexpr int SM1 = StageCfg<false>::SMEM;   // 61440
    constexpr int SMT = StageCfg<true>::SMEM;    // 56832
    cudaFuncSetAttribute((const void*)tgemm<EPI_BIAS_ADDX, 0>, cudaFuncAttributeMaxDynamicSharedMemorySize, SM1);
    cudaFuncSetAttribute((const void*)tgemm<EPI_BIAS_RELU, 1>, cudaFuncAttributeMaxDynamicSharedMemorySize, SM1);
    cudaFuncSetAttribute((const void*)tgemm<EPI_NONE, 1>,      cudaFuncAttributeMaxDynamicSharedMemorySize, SM1);
    cudaFuncSetAttribute((const void*)tgemm<EPI_RELUSQ, 1>,    cudaFuncAttributeMaxDynamicSharedMemorySize, SM1);
    cudaFuncSetAttribute((const void*)tgemm<EPI_GATE, 1, true>,cudaFuncAttributeMaxDynamicSharedMemorySize, SMT);
    cudaFuncSetAttribute((const void*)tgemm<EPI_BIAS, 0>,      cudaFuncAttributeMaxDynamicSharedMemorySize, SM1);

    cudaStream_t s1;
    cudaEvent_t eS, e0, eW, eJ;
    cudaStreamCreateWithFlags(&s1, cudaStreamNonBlocking);
    cudaEventCreateWithFlags(&eS, cudaEventDisableTiming);
    cudaEventCreateWithFlags(&e0, cudaEventDisableTiming);
    cudaEventCreateWithFlags(&eW, cudaEventDisableTiming);
    cudaEventCreateWithFlags(&eJ, cudaEventDisableTiming);

    const float inv_s = 1.0f / (float)Sn;

    // fork s1 from the capturing stream FIRST (required for graph capture)
    cudaEventRecord(eS, 0);
    cudaStreamWaitEvent(s1, eS, 0);

    // s1: weight conversions (Wh, Wq, Wo, WbT)
    cvt_rest_kernel<<<(Q_REST + 255) / 256, 256, 0, s1>>>(Wh, Whh, Wq, Wqh, Wo, Woh);
    cvt_tr_kernel<<<dim3(QKDn / 32, QKDn / 32, 1), 256, 0, s1>>>(Wb, WbTh, QKDn, QKDn);
    cudaEventRecord(eW, s1);

    // s0: x/Wm conversion -> GEMM1 -> LN1
    cvt_xm_kernel<<<(Q_XM + 255) / 256, 256>>>(x, xh, Wm, Wmh);

    tgemm<EPI_BIAS_ADDX, 0><<<Dn / 128 * (BSn / 128), 128, SM1>>>(
        xh, Wmh, bm, x, tmp1, nullptr,
        Dn, Dn, Dn, Dn, 0, 0, 0, 0, Dn, 1.0f,
        Dn / 128, BSn / 128, 1);

    ln_kernel<true><<<BSn, 256>>>(tmp1, g1, b1, nullptr, nullptr, nh);
    cudaEventRecord(e0, 0);

    // s1 branch: Z -> ZW -> QK (needs nh; weights already converted on s1)
    cudaStreamWaitEvent(s1, e0, 0);

    tgemm<EPI_BIAS_RELU, 1><<<QKDn / 128 * (BSn / 128), 128, SM1, s1>>>(
        nh, Wqh, bq, nullptr, nullptr, Zh,
        Dn, Dn, Dn, QKDn, 0, 0, 0, 0, 0, 1.0f,
        QKDn / 128, BSn / 128, 1);

    tgemm<EPI_NONE, 1><<<QKDn / 128 * (BSn / 128), 128, SM1, s1>>>(
        Zh, WbTh, nullptr, nullptr, nullptr, ZWh,
        QKDn, QKDn, QKDn, QKDn, 0, 0, 0, 0, 0, 1.0f,
        QKDn / 128, BSn / 128, 1);

    tgemm<EPI_RELUSQ, 1><<<Sn / 128 * (Sn / 128) * Bn, 128, SM1, s1>>>(
        ZWh, Zh, nullptr, nullptr, nullptr, Amh,
        QKDn, QKDn, QKDn, Sn,
        (long long)Sn * QKDn, (long long)Sn * QKDn, (long long)Sn * Sn, 0, 0, inv_s,
        Sn / 128, Sn / 128, Bn);

    cudaEventRecord(eJ, s1);

    // s0: Wh GEMM (overlaps s1 chain), needs Whh
    cudaStreamWaitEvent(0, eW, 0);
    tgemm<EPI_BIAS_RELU, 1><<<2 * HIDn / 128 * (BSn / 128), 128, SM1>>>(
        nh, Whh, bh, nullptr, nullptr, hb,
        Dn, Dn, Dn, 2 * HIDn, 0, 0, 0, 0, 0, 1.0f,
        2 * HIDn / 128, BSn / 128, 1);

    // join QK chain
    cudaStreamWaitEvent(0, eJ, 0);

    // V = (A @ v) * gate — persistent grid (296 = 148 SM x 2 CTA) over 768 tiles
    tgemm<EPI_GATE, 1, true><<<296, 128, SMT>>>(
        Amh, hb, nullptr, hb + HIDn, nullptr, Vh,
        Sn, Sn, 2 * HIDn, HIDn,
        (long long)Sn * Sn, (long long)Sn * 2 * HIDn, (long long)Sn * HIDn,
        (long long)Sn * 2 * HIDn, 2 * HIDn, 1.0f,
        HIDn / 128, Sn / 128, Bn);

    // U = V @ Wo^T + bo
    tgemm<EPI_BIAS, 0><<<Dn / 128 * (BSn / 128), 128, SM1>>>(
        Vh, Woh, bo, nullptr, U, nullptr,
        HIDn, HIDn, HIDn, Dn, 0, 0, 0, 0, 0, 1.0f,
        Dn / 128, BSn / 128, 1);

    // out = LN(U) + x
    ln_kernel<false><<<BSn, 256>>>(U, g2, b2, x, out, nullptr);
}

// round 13
// speedup vs baseline: 1.0533x; 1.0533x over previous
#include <cuda_runtime.h>
#include <cuda_fp16.h>
#include <cstdint>

// GAU block on GB300 (plain sm_103 target): fp16 1-pass GEMMs on
// mma.sync.m16n8k16 + ldmatrix + cp.async.
// R13 = R10 GEMM (non-persistent 3D grid; low regs, 2 CTA/SM) + R12 schedule
// (capture-legal fork, split converters overlapped on side stream).
// B=4, S=2048, D=512, QKD=256, HID=1536

constexpr int Bn = 4, Sn = 2048, Dn = 512, QKDn = 256, HIDn = 1536;
constexpr int BSn = Bn * Sn;                 // 8192
constexpr float LN_EPS = 1e-5f;

// ----------------------------------------------------------------------------
// scratch (device globals)
// ----------------------------------------------------------------------------
static __device__ __align__(16) __half g_xh[BSn * Dn];
static __device__ __align__(16) __half g_Wmh[Dn * Dn];
static __device__ __align__(16) __half g_Whh[2 * HIDn * Dn];
static __device__ __align__(16) __half g_Wqh[QKDn * Dn];
static __device__ __align__(16) __half g_Woh[Dn * HIDn];
static __device__ __align__(16) __half g_WbTh[QKDn * QKDn];
static __device__ __align__(16) float  g_tmp1[BSn * Dn];
static __device__ __align__(16) __half g_nh[BSn * Dn];
static __device__ __align__(16) __half g_hbuf[BSn * 2 * HIDn];          // [v | gate]
static __device__ __align__(16) __half g_Zh[BSn * QKDn];
static __device__ __align__(16) __half g_ZWh[BSn * QKDn];
static __device__ __align__(16) __half g_Amh[(long long)Bn * Sn * Sn];
static __device__ __align__(16) __half g_Vh[BSn * HIDn];
static __device__ __align__(16) float  g_U[BSn * Dn];

// ----------------------------------------------------------------------------
// PTX helpers
// ----------------------------------------------------------------------------
__device__ __forceinline__ uint32_t smem_u32(const void* p) {
    uint32_t a;
    asm("{ .reg .u64 t; cvta.to.shared.u64 t, %1; cvt.u32.u64 %0, t; }"
        : "=r"(a) : "l"(p));
    return a;
}
__device__ __forceinline__ void cpa16(uint32_t saddr, const void* gaddr) {
    asm volatile("cp.async.cg.shared.global [%0], [%1], 16;"
                 :: "r"(saddr), "l"(gaddr) : "memory");
}
__device__ __forceinline__ void cpa_commit() {
    asm volatile("cp.async.commit_group;" ::: "memory");
}
template<int N>
__device__ __forceinline__ void cpa_wait() {
    asm volatile("cp.async.wait_group %0;" :: "n"(N) : "memory");
}
__device__ __forceinline__ void ldm_x4(uint32_t a, uint32_t& r0, uint32_t& r1,
                                       uint32_t& r2, uint32_t& r3) {
    asm volatile("ldmatrix.sync.aligned.m8n8.x4.shared.b16 {%0,%1,%2,%3}, [%4];"
                 : "=r"(r0), "=r"(r1), "=r"(r2), "=r"(r3) : "r"(a));
}
__device__ __forceinline__ void ldm_x4_trans(uint32_t a, uint32_t& r0, uint32_t& r1,
                                             uint32_t& r2, uint32_t& r3) {
    asm volatile("ldmatrix.sync.aligned.m8n8.x4.trans.shared.b16 {%0,%1,%2,%3}, [%4];"
                 : "=r"(r0), "=r"(r1), "=r"(r2), "=r"(r3) : "r"(a));
}
__device__ __forceinline__ void mma_f16(float* c, const uint32_t* a, uint32_t b0, uint32_t b1) {
    asm volatile(
        "mma.sync.aligned.m16n8k16.row.col.f32.f16.f16.f32 "
        "{%0,%1,%2,%3}, {%4,%5,%6,%7}, {%8,%9}, {%0,%1,%2,%3};"
        : "+f"(c[0]), "+f"(c[1]), "+f"(c[2]), "+f"(c[3])
        : "r"(a[0]), "r"(a[1]), "r"(a[2]), "r"(a[3]), "r"(b0), "r"(b1));
}
__device__ __forceinline__ uint32_t pack2(__half a, __half b) {
    return (uint32_t)__half_as_ushort(a) | ((uint32_t)__half_as_ushort(b) << 16);
}

// ----------------------------------------------------------------------------
// tensor GEMM (1-pass): C[m,n] = sum_k A[m,k]*B[n,k]
// A K-major. B: TRB==false -> K-major; TRB==true -> N-major (ldmatrix.trans).
// CTA tile 128x128, K-tile 32, 4 warps (2x2, 64x64 warp tiles), 3-stage pipe.
// OUT: 0 = fp32, 1 = fp16.  EPI_GATE extra fp16, EPI_BIAS_ADDX extra fp32.
// ----------------------------------------------------------------------------
enum { EPI_NONE = 0, EPI_BIAS = 1, EPI_BIAS_RELU = 2, EPI_BIAS_ADDX = 3,
       EPI_RELUSQ = 4, EPI_GATE = 5 };

constexpr int TROW = 80;
constexpr int TILE_B = 128 * TROW;             // 10240
constexpr int TRB_ROW = 272;
constexpr int TRB_TILE = 32 * TRB_ROW;         // 8704
template<bool TRB> struct StageCfg {
    static constexpr int STAGE_B = TILE_B + (TRB ? TRB_TILE : TILE_B);
    static constexpr int SMEM = 3 * STAGE_B;
};

__device__ __forceinline__ void fill_tile(uint32_t sbase,
                                          const __half* __restrict__ g,
                                          long long row0, int ld, long long k0, int tid)
{
    #pragma unroll
    for (int it = 0; it < 4; ++it) {
        int q = tid + it * 128;
        int r = q >> 2, c = q & 3;
        cpa16(sbase + r * TROW + c * 16,
              g + (row0 + r) * (long long)ld + k0 + c * 8);
    }
}

__device__ __forceinline__ void fill_tile_trb(uint32_t sbase,
                                              const __half* __restrict__ g,
                                              long long n0, int ld, long long k0, int tid)
{
    #pragma unroll
    for (int it = 0; it < 4; ++it) {
        int q = tid + it * 128;
        int r = q >> 4, c = q & 15;
        cpa16(sbase + r * TRB_ROW + c * 16,
              g + (k0 + r) * (long long)ld + n0 + c * 8);
    }
}

template<int EPI, int OUT, bool TRB = false>
__global__ void __launch_bounds__(128, 2)
tgemm(const __half* __restrict__ pA,
      const __half* __restrict__ pB,
      const float* __restrict__ bias, const void* __restrict__ extra,
      float* __restrict__ Cf, __half* __restrict__ Ch,
      int K, int lda, int ldb, int ldc,
      long long sA, long long sB, long long sC, long long sE,
      int lde, float scale)
{
    constexpr int STAGE_B = StageCfg<TRB>::STAGE_B;
    extern __shared__ char smem[];
    const int tid = threadIdx.x;
    const int wid = tid >> 5, lane = tid & 31;
    const int z = blockIdx.z;
    pA += (long long)z * sA;
    pB += (long long)z * sB;
    const float*  Exf = (EPI == EPI_BIAS_ADDX && extra)
                        ? (const float*)extra + (long long)z * sE : nullptr;
    const __half* Exh = (EPI == EPI_GATE && extra)
                        ? (const __half*)extra + (long long)z * sE : nullptr;
    const long long coff = (long long)z * sC;
    const long long m0 = (long long)blockIdx.y * 128;
    const long long n0 = (long long)blockIdx.x * 128;
    const uint32_t sb = smem_u32(smem);

    const int wm = (wid >> 1) * 64;
    const int wn = (wid & 1) * 64;
    const int rowL = (lane & 7) + ((lane >> 3) & 1) * 8;
    const int cOff = lane >> 4;

    float acc[4][8][4];
    #pragma unroll
    for (int i = 0; i < 4; ++i)
        #pragma unroll
        for (int j = 0; j < 8; ++j)
            #pragma unroll
            for (int t = 0; t < 4; ++t) acc[i][j][t] = 0.0f;

    const int KT = K >> 5;

    auto fill_stage = [&](int stage, long long k0) {
        uint32_t s = sb + stage * STAGE_B;
        fill_tile(s, pA, m0, lda, k0, tid);
        if (TRB) fill_tile_trb(s + TILE_B, pB, n0, ldb, k0, tid);
        else     fill_tile(s + TILE_B, pB, n0, ldb, k0, tid);
    };

    // prologue: 2 stages ahead
    #pragma unroll
    for (int s = 0; s < 2; ++s) {
        fill_stage(s, (long long)s * 32);
        cpa_commit();
    }

    for (int kt = 0; kt < KT; ++kt) {
        const int fs = kt + 2;
        if (fs < KT) fill_stage(fs % 3, (long long)fs * 32);
        cpa_commit();
        cpa_wait<2>();
        __syncthreads();

        const uint32_t st = sb + (kt % 3) * STAGE_B;
        const uint32_t aB = st;
        const uint32_t bB = st + TILE_B;

        #pragma unroll
        for (int kk = 0; kk < 2; ++kk) {
            const int cc = kk * 2 + cOff;
            uint32_t ah[4][4];
            #pragma unroll
            for (int im = 0; im < 4; ++im) {
                uint32_t off = (uint32_t)((wm + im * 16 + rowL) * TROW + cc * 16);
                ldm_x4(aB + off, ah[im][0], ah[im][1], ah[im][2], ah[im][3]);
            }
            uint32_t bh[4][4];
            #pragma unroll
            for (int nb = 0; nb < 4; ++nb) {
                if (TRB) {
                    uint32_t off = (uint32_t)(
                        (kk * 16 + ((lane >> 4) & 1) * 8 + (lane & 7)) * TRB_ROW +
                        (wn + nb * 16 + ((lane >> 3) & 1) * 8) * 2);
                    ldm_x4_trans(bB + off, bh[nb][0], bh[nb][1], bh[nb][2], bh[nb][3]);
                } else {
                    uint32_t off = (uint32_t)((wn + nb * 16 + rowL) * TROW + cc * 16);
                    ldm_x4(bB + off, bh[nb][0], bh[nb][1], bh[nb][2], bh[nb][3]);
                }
            }
            #pragma unroll
            for (int im = 0; im < 4; ++im) {
                #pragma unroll
                for (int j = 0; j < 8; ++j) {
                    const int nb = j >> 1, sel = j & 1;
                    mma_f16(acc[im][j], ah[im], bh[nb][sel], bh[nb][sel + 2]);
                }
            }
        }
        __syncthreads();
    }

    // ---- epilogue ----
    const int rql = lane >> 2;
    const int cql = (lane & 3) * 2;

    #pragma unroll
    for (int im = 0; im < 4; ++im) {
        #pragma unroll
        for (int j = 0; j < 8; ++j) {
            #pragma unroll
            for (int half = 0; half < 2; ++half) {
                const long long gm = m0 + wm + im * 16 + rql + half * 8;
                const long long gn = n0 + wn + j * 8 + cql;
                float v0 = acc[im][j][half * 2 + 0];
                float v1 = acc[im][j][half * 2 + 1];

                if (EPI == EPI_BIAS || EPI == EPI_BIAS_RELU || EPI == EPI_BIAS_ADDX) {
                    float2 bv = *reinterpret_cast<const float2*>(&bias[gn]);
                    v0 += bv.x; v1 += bv.y;
                }
                if (EPI == EPI_BIAS_RELU) { v0 = fmaxf(v0, 0.0f); v1 = fmaxf(v1, 0.0f); }
                if (EPI == EPI_BIAS_ADDX) {
                    float2 ev = *reinterpret_cast<const float2*>(&Exf[gm * lde + gn]);
                    v0 += ev.x; v1 += ev.y;
                }
                if (EPI == EPI_GATE) {
                    uint32_t gp = *reinterpret_cast<const uint32_t*>(&Exh[gm * lde + gn]);
                    v0 *= __half2float(__ushort_as_half((unsigned short)(gp & 0xFFFF)));
                    v1 *= __half2float(__ushort_as_half((unsigned short)(gp >> 16)));
                }
                if (EPI == EPI_RELUSQ) {
                    float r0 = fmaxf(v0 * scale, 0.0f), r1 = fmaxf(v1 * scale, 0.0f);
                    v0 = r0 * r0; v1 = r1 * r1;
                }

                const long long oi = coff + gm * ldc + gn;
                if (OUT == 0) {
                    *reinterpret_cast<float2*>(&Cf[oi]) = make_float2(v0, v1);
                } else {
                    *reinterpret_cast<uint32_t*>(&Ch[oi]) =
                        pack2(__float2half_rn(v0), __float2half_rn(v1));
                }
            }
        }
    }
}

// ----------------------------------------------------------------------------
// LayerNorm (D=512)
// ----------------------------------------------------------------------------
__device__ __forceinline__ float block_sum_512(float v, float* red)
{
    #pragma unroll
    for (int o = 16; o > 0; o >>= 1) v += __shfl_down_sync(0xffffffffu, v, o);
    if ((threadIdx.x & 31) == 0) red[threadIdx.x >> 5] = v;
    __syncthreads();
    if (threadIdx.x == 0) {
        float s = 0.0f;
        #pragma unroll
        for (int i = 0; i < 8; i++) s += red[i];
        red[0] = s;
    }
    __syncthreads();
    float r = red[0];
    __syncthreads();
    return r;
}

template<bool HALF_OUT>
__global__ void __launch_bounds__(256)
ln_kernel(const float* __restrict__ in, const float* __restrict__ g,
          const float* __restrict__ b, const float* __restrict__ resid,
          float* __restrict__ outf, __half* __restrict__ oh)
{
    __shared__ float red[8];
    const long long row = blockIdx.x;
    const int t = threadIdx.x;
    const float* rp = in + row * Dn;

    float v0 = rp[t], v1 = rp[t + 256];
    float mean = block_sum_512(v0 + v1, red) * (1.0f / Dn);
    float d0 = v0 - mean, d1 = v1 - mean;
    float var = block_sum_512(d0 * d0 + d1 * d1, red) * (1.0f / Dn);
    float inv = rsqrtf(var + LN_EPS);

    float o0 = d0 * inv * g[t]       + b[t];
    float o1 = d1 * inv * g[t + 256] + b[t + 256];
    if (HALF_OUT) {
        oh[row * Dn + t]       = __float2half_rn(o0);
        oh[row * Dn + t + 256] = __float2half_rn(o1);
    } else {
        if (resid) {
            o0 += resid[row * Dn + t];
            o1 += resid[row * Dn + t + 256];
        }
        outf[row * Dn + t]       = o0;
        outf[row * Dn + t + 256] = o1;
    }
}

// ----------------------------------------------------------------------------
// converters
// ----------------------------------------------------------------------------
constexpr int Q_X  = BSn * Dn / 4;
constexpr int Q_WM = Dn * Dn / 4;
constexpr int Q_WH = 2 * HIDn * Dn / 4;
constexpr int Q_WQ = QKDn * Dn / 4;
constexpr int Q_WO = Dn * HIDn / 4;
constexpr int Q_XM   = Q_X + Q_WM;
constexpr int Q_REST = Q_WH + Q_WQ + Q_WO;

__global__ void __launch_bounds__(256)
cvt_xm_kernel(const float* __restrict__ x,  __half* xh,
              const float* __restrict__ wm, __half* wmh)
{
    int i = blockIdx.x * 256 + threadIdx.x;
    if (i >= Q_XM) return;
    const float* in; __half* oh;
    if (i < Q_X) { in = x; oh = xh; }
    else         { i -= Q_X; in = wm; oh = wmh; }
    float4 v = reinterpret_cast<const float4*>(in)[i];
    reinterpret_cast<uint2*>(oh)[i] = make_uint2(
        pack2(__float2half_rn(v.x), __float2half_rn(v.y)),
        pack2(__float2half_rn(v.z), __float2half_rn(v.w)));
}

__global__ void __launch_bounds__(256)
cvt_rest_kernel(const float* __restrict__ wh, __half* whh,
                const float* __restrict__ wq, __half* wqh,
                const float* __restrict__ wo, __half* woh)
{
    int i = blockIdx.x * 256 + threadIdx.x;
    if (i >= Q_REST) return;
    const float* in; __half* oh;
    if (i < Q_WH)                { in = wh; oh = whh; }
    else if ((i -= Q_WH) < Q_WQ) { in = wq; oh = wqh; }
    else     { i -= Q_WQ;          in = wo; oh = woh; }
    float4 v = reinterpret_cast<const float4*>(in)[i];
    reinterpret_cast<uint2*>(oh)[i] = make_uint2(
        pack2(__float2half_rn(v.x), __float2half_rn(v.y)),
        pack2(__float2half_rn(v.z), __float2half_rn(v.w)));
}

// transpose (fp32 in, fp16 out): out[c][r] = in[r][c]   (Wb only)
__global__ void __launch_bounds__(256)
cvt_tr_kernel(const float* __restrict__ in, __half* __restrict__ oh,
              int ldin, int ldout)
{
    __shared__ float tbuf[32][33];
    const int c0 = blockIdx.x * 32, r0 = blockIdx.y * 32;
    const int tx = threadIdx.x & 31, ty = threadIdx.x >> 5;

    #pragma unroll
    for (int i = 0; i < 4; i++)
        tbuf[ty + i * 8][tx] = in[(long long)(r0 + ty + i * 8) * ldin + c0 + tx];
    __syncthreads();
    #pragma unroll
    for (int i = 0; i < 4; i++) {
        float v = tbuf[tx][ty + i * 8];
        long long oi = (long long)(c0 + ty + i * 8) * ldout + r0 + tx;
        oh[oi] = __float2half_rn(v);
    }
}

// ----------------------------------------------------------------------------
// launch
// ----------------------------------------------------------------------------
extern "C" void kernel_launch(void* const* d_in, const int* in_sizes, int n_in,
                              void* d_out, int out_size)
{
    const float* x  = (const float*)d_in[0];
    const float* Wm = (const float*)d_in[1];
    const float* bm = (const float*)d_in[2];
    const float* g1 = (const float*)d_in[3];
    const float* b1 = (const float*)d_in[4];
    const float* Wh = (const float*)d_in[5];
    const float* bh = (const float*)d_in[6];
    const float* Wq = (const float*)d_in[7];
    const float* bq = (const float*)d_in[8];
    const float* Wb = (const float*)d_in[9];
    const float* Wo = (const float*)d_in[10];
    const float* bo = (const float*)d_in[11];
    const float* g2 = (const float*)d_in[12];
    const float* b2 = (const float*)d_in[13];
    float* out = (float*)d_out;

    __half *xh, *Wmh, *Whh, *Wqh, *Woh, *WbTh;
    __half *nh, *Zh, *ZWh, *Amh, *Vh, *hb;
    float *tmp1, *U;
    cudaGetSymbolAddress((void**)&xh, g_xh);
    cudaGetSymbolAddress((void**)&Wmh, g_Wmh);
    cudaGetSymbolAddress((void**)&Whh, g_Whh);
    cudaGetSymbolAddress((void**)&Wqh, g_Wqh);
    cudaGetSymbolAddress((void**)&Woh, g_Woh);
    cudaGetSymbolAddress((void**)&WbTh, g_WbTh);
    cudaGetSymbolAddress((void**)&nh, g_nh);
    cudaGetSymbolAddress((void**)&Zh, g_Zh);
    cudaGetSymbolAddress((void**)&ZWh, g_ZWh);
    cudaGetSymbolAddress((void**)&Amh, g_Amh);
    cudaGetSymbolAddress((void**)&Vh, g_Vh);
    cudaGetSymbolAddress((void**)&hb, g_hbuf);
    cudaGetSymbolAddress((void**)&tmp1, g_tmp1);
    cudaGetSymbolAddress((void**)&U, g_U);

    constexpr int SM1 = StageCfg<false>::SMEM;   // 61440
    constexpr int SMT = StageCfg<true>::SMEM;    // 56832
    cudaFuncSetAttribute((const void*)tgemm<EPI_BIAS_ADDX, 0>, cudaFuncAttributeMaxDynamicSharedMemorySize, SM1);
    cudaFuncSetAttribute((const void*)tgemm<EPI_BIAS_RELU, 1>, cudaFuncAttributeMaxDynamicSharedMemorySize, SM1);
    cudaFuncSetAttribute((const void*)tgemm<EPI_NONE, 1>,      cudaFuncAttributeMaxDynamicSharedMemorySize, SM1);
    cudaFuncSetAttribute((const void*)tgemm<EPI_RELUSQ, 1>,    cudaFuncAttributeMaxDynamicSharedMemorySize, SM1);
    cudaFuncSetAttribute((const void*)tgemm<EPI_GATE, 1, true>,cudaFuncAttributeMaxDynamicSharedMemorySize, SMT);
    cudaFuncSetAttribute((const void*)tgemm<EPI_BIAS, 0>,      cudaFuncAttributeMaxDynamicSharedMemorySize, SM1);

    cudaStream_t s1;
    cudaEvent_t eS, e0, eW, eJ;
    cudaStreamCreateWithFlags(&s1, cudaStreamNonBlocking);
    cudaEventCreateWithFlags(&eS, cudaEventDisableTiming);
    cudaEventCreateWithFlags(&e0, cudaEventDisableTiming);
    cudaEventCreateWithFlags(&eW, cudaEventDisableTiming);
    cudaEventCreateWithFlags(&eJ, cudaEventDisableTiming);

    const float inv_s = 1.0f / (float)Sn;

    // fork s1 from the capturing stream FIRST (required for graph capture)
    cudaEventRecord(eS, 0);
    cudaStreamWaitEvent(s1, eS, 0);

    // s1: weight conversions (Wh, Wq, Wo, WbT)
    cvt_rest_kernel<<<(Q_REST + 255) / 256, 256, 0, s1>>>(Wh, Whh, Wq, Wqh, Wo, Woh);
    cvt_tr_kernel<<<dim3(QKDn / 32, QKDn / 32, 1), 256, 0, s1>>>(Wb, WbTh, QKDn, QKDn);
    cudaEventRecord(eW, s1);

    // s0: x/Wm conversion -> GEMM1 -> LN1
    cvt_xm_kernel<<<(Q_XM + 255) / 256, 256>>>(x, xh, Wm, Wmh);

    tgemm<EPI_BIAS_ADDX, 0><<<dim3(Dn / 128, BSn / 128, 1), 128, SM1>>>(
        xh, Wmh, bm, x, tmp1, nullptr,
        Dn, Dn, Dn, Dn, 0, 0, 0, 0, Dn, 1.0f);

    ln_kernel<true><<<BSn, 256>>>(tmp1, g1, b1, nullptr, nullptr, nh);
    cudaEventRecord(e0, 0);

    // s1 branch: Z -> ZW -> QK (needs nh; weights already converted on s1)
    cudaStreamWaitEvent(s1, e0, 0);

    tgemm<EPI_BIAS_RELU, 1><<<dim3(QKDn / 128, BSn / 128, 1), 128, SM1, s1>>>(
        nh, Wqh, bq, nullptr, nullptr, Zh,
        Dn, Dn, Dn, QKDn, 0, 0, 0, 0, 0, 1.0f);

    tgemm<EPI_NONE, 1><<<dim3(QKDn / 128, BSn / 128, 1), 128, SM1, s1>>>(
        Zh, WbTh, nullptr, nullptr, nullptr, ZWh,
        QKDn, QKDn, QKDn, QKDn, 0, 0, 0, 0, 0, 1.0f);

    tgemm<EPI_RELUSQ, 1><<<dim3(Sn / 128, Sn / 128, Bn), 128, SM1, s1>>>(
        ZWh, Zh, nullptr, nullptr, nullptr, Amh,
        QKDn, QKDn, QKDn, Sn,
        (long long)Sn * QKDn, (long long)Sn * QKDn, (long long)Sn * Sn, 0, 0, inv_s);

    cudaEventRecord(eJ, s1);

    // s0: Wh GEMM (overlaps s1 chain), needs Whh
    cudaStreamWaitEvent(0, eW, 0);
    tgemm<EPI_BIAS_RELU, 1><<<dim3(2 * HIDn / 128, BSn / 128, 1), 128, SM1>>>(
        nh, Whh, bh, nullptr, nullptr, hb,
        Dn, Dn, Dn, 2 * HIDn, 0, 0, 0, 0, 0, 1.0f);

    // join QK chain
    cudaStreamWaitEvent(0, eJ, 0);

    // V = (A @ v) * gate   (v read in-place from hb via ldmatrix.trans)
    tgemm<EPI_GATE, 1, true><<<dim3(HIDn / 128, Sn / 128, Bn), 128, SMT>>>(
        Amh, hb, nullptr, hb + HIDn, nullptr, Vh,
        Sn, Sn, 2 * HIDn, HIDn,
        (long long)Sn * Sn, (long long)Sn * 2 * HIDn, (long long)Sn * HIDn,
        (long long)Sn * 2 * HIDn, 2 * HIDn, 1.0f);

    // U = V @ Wo^T + bo
    tgemm<EPI_BIAS, 0><<<dim3(Dn / 128, BSn / 128, 1), 128, SM1>>>(
        Vh, Woh, bo, nullptr, U, nullptr,
        HIDn, HIDn, HIDn, Dn, 0, 0, 0, 0, 0, 1.0f);

    // out = LN(U) + x
    ln_kernel<false><<<BSn, 256>>>(U, g2, b2, x, out, nullptr);
}

// round 14
// speedup vs baseline: 1.1467x; 1.0886x over previous
#include <cuda_runtime.h>
#include <cuda_fp16.h>
#include <cstdint>

// GAU block on GB300 (plain sm_103 target): fp16 1-pass GEMMs on
// mma.sync.m16n8k16 + ldmatrix + cp.async.
// R14 = R10 schedule + K-tile 64 (halves per-iteration sync/wait overhead).
// B=4, S=2048, D=512, QKD=256, HID=1536

constexpr int Bn = 4, Sn = 2048, Dn = 512, QKDn = 256, HIDn = 1536;
constexpr int BSn = Bn * Sn;                 // 8192
constexpr float LN_EPS = 1e-5f;

// ----------------------------------------------------------------------------
// scratch (device globals)
// ----------------------------------------------------------------------------
static __device__ __align__(16) __half g_xh[BSn * Dn];
static __device__ __align__(16) __half g_Wmh[Dn * Dn];
static __device__ __align__(16) __half g_Whh[2 * HIDn * Dn];
static __device__ __align__(16) __half g_Wqh[QKDn * Dn];
static __device__ __align__(16) __half g_Woh[Dn * HIDn];
static __device__ __align__(16) __half g_WbTh[QKDn * QKDn];
static __device__ __align__(16) float  g_tmp1[BSn * Dn];
static __device__ __align__(16) __half g_nh[BSn * Dn];
static __device__ __align__(16) __half g_hbuf[BSn * 2 * HIDn];          // [v | gate]
static __device__ __align__(16) __half g_Zh[BSn * QKDn];
static __device__ __align__(16) __half g_ZWh[BSn * QKDn];
static __device__ __align__(16) __half g_Amh[(long long)Bn * Sn * Sn];
static __device__ __align__(16) __half g_Vh[BSn * HIDn];
static __device__ __align__(16) float  g_U[BSn * Dn];

// ----------------------------------------------------------------------------
// PTX helpers
// ----------------------------------------------------------------------------
__device__ __forceinline__ uint32_t smem_u32(const void* p) {
    uint32_t a;
    asm("{ .reg .u64 t; cvta.to.shared.u64 t, %1; cvt.u32.u64 %0, t; }"
        : "=r"(a) : "l"(p));
    return a;
}
__device__ __forceinline__ void cpa16(uint32_t saddr, const void* gaddr) {
    asm volatile("cp.async.cg.shared.global [%0], [%1], 16;"
                 :: "r"(saddr), "l"(gaddr) : "memory");
}
__device__ __forceinline__ void cpa_commit() {
    asm volatile("cp.async.commit_group;" ::: "memory");
}
template<int N>
__device__ __forceinline__ void cpa_wait() {
    asm volatile("cp.async.wait_group %0;" :: "n"(N) : "memory");
}
__device__ __forceinline__ void ldm_x4(uint32_t a, uint32_t& r0, uint32_t& r1,
                                       uint32_t& r2, uint32_t& r3) {
    asm volatile("ldmatrix.sync.aligned.m8n8.x4.shared.b16 {%0,%1,%2,%3}, [%4];"
                 : "=r"(r0), "=r"(r1), "=r"(r2), "=r"(r3) : "r"(a));
}
__device__ __forceinline__ void ldm_x4_trans(uint32_t a, uint32_t& r0, uint32_t& r1,
                                             uint32_t& r2, uint32_t& r3) {
    asm volatile("ldmatrix.sync.aligned.m8n8.x4.trans.shared.b16 {%0,%1,%2,%3}, [%4];"
                 : "=r"(r0), "=r"(r1), "=r"(r2), "=r"(r3) : "r"(a));
}
__device__ __forceinline__ void mma_f16(float* c, const uint32_t* a, uint32_t b0, uint32_t b1) {
    asm volatile(
        "mma.sync.aligned.m16n8k16.row.col.f32.f16.f16.f32 "
        "{%0,%1,%2,%3}, {%4,%5,%6,%7}, {%8,%9}, {%0,%1,%2,%3};"
        : "+f"(c[0]), "+f"(c[1]), "+f"(c[2]), "+f"(c[3])
        : "r"(a[0]), "r"(a[1]), "r"(a[2]), "r"(a[3]), "r"(b0), "r"(b1));
}
__device__ __forceinline__ uint32_t pack2(__half a, __half b) {
    return (uint32_t)__half_as_ushort(a) | ((uint32_t)__half_as_ushort(b) << 16);
}

// ----------------------------------------------------------------------------
// tensor GEMM (1-pass): C[m,n] = sum_k A[m,k]*B[n,k]
// A K-major. B: TRB==false -> K-major; TRB==true -> N-major (ldmatrix.trans).
// CTA tile 128x128, K-tile 64, 4 warps (2x2, 64x64 warp tiles), 3-stage pipe.
// OUT: 0 = fp32, 1 = fp16.  EPI_GATE extra fp16, EPI_BIAS_ADDX extra fp32.
// ----------------------------------------------------------------------------
enum { EPI_NONE = 0, EPI_BIAS = 1, EPI_BIAS_RELU = 2, EPI_BIAS_ADDX = 3,
       EPI_RELUSQ = 4, EPI_GATE = 5 };

constexpr int TROW = 144;                      // 128B data + 16B pad
constexpr int TILE_B = 128 * TROW;             // 18432
constexpr int TRB_ROW = 272;                   // 256B data + 16B pad
constexpr int TRB_TILE = 64 * TRB_ROW;         // 17408
template<bool TRB> struct StageCfg {
    static constexpr int STAGE_B = TILE_B + (TRB ? TRB_TILE : TILE_B);
    static constexpr int SMEM = 3 * STAGE_B;   // 110592 / 107520
};

// K-major tile: 128 rows x 128B (64 halves), padded stride 144B
__device__ __forceinline__ void fill_tile(uint32_t sbase,
                                          const __half* __restrict__ g,
                                          long long row0, int ld, long long k0, int tid)
{
    #pragma unroll
    for (int it = 0; it < 8; ++it) {
        int q = tid + it * 128;               // 1024 chunks of 16B
        int r = q >> 3, c = q & 7;
        cpa16(sbase + r * TROW + c * 16,
              g + (row0 + r) * (long long)ld + k0 + c * 8);
    }
}

// N-major tile: 64 k-rows x 256B (128 halves), padded stride 272B
__device__ __forceinline__ void fill_tile_trb(uint32_t sbase,
                                              const __half* __restrict__ g,
                                              long long n0, int ld, long long k0, int tid)
{
    #pragma unroll
    for (int it = 0; it < 8; ++it) {
        int q = tid + it * 128;               // 1024 chunks of 16B
        int r = q >> 4, c = q & 15;
        cpa16(sbase + r * TRB_ROW + c * 16,
              g + (k0 + r) * (long long)ld + n0 + c * 8);
    }
}

template<int EPI, int OUT, bool TRB = false>
__global__ void __launch_bounds__(128, 2)
tgemm(const __half* __restrict__ pA,
      const __half* __restrict__ pB,
      const float* __restrict__ bias, const void* __restrict__ extra,
      float* __restrict__ Cf, __half* __restrict__ Ch,
      int K, int lda, int ldb, int ldc,
      long long sA, long long sB, long long sC, long long sE,
      int lde, float scale)
{
    constexpr int STAGE_B = StageCfg<TRB>::STAGE_B;
    extern __shared__ char smem[];
    const int tid = threadIdx.x;
    const int wid = tid >> 5, lane = tid & 31;
    const int z = blockIdx.z;
    pA += (long long)z * sA;
    pB += (long long)z * sB;
    const float*  Exf = (EPI == EPI_BIAS_ADDX && extra)
                        ? (const float*)extra + (long long)z * sE : nullptr;
    const __half* Exh = (EPI == EPI_GATE && extra)
                        ? (const __half*)extra + (long long)z * sE : nullptr;
    const long long coff = (long long)z * sC;
    const long long m0 = (long long)blockIdx.y * 128;
    const long long n0 = (long long)blockIdx.x * 128;
    const uint32_t sb = smem_u32(smem);

    const int wm = (wid >> 1) * 64;
    const int wn = (wid & 1) * 64;
    const int rowL = (lane & 7) + ((lane >> 3) & 1) * 8;
    const int cOff = lane >> 4;

    float acc[4][8][4];
    #pragma unroll
    for (int i = 0; i < 4; ++i)
        #pragma unroll
        for (int j = 0; j < 8; ++j)
            #pragma unroll
            for (int t = 0; t < 4; ++t) acc[i][j][t] = 0.0f;

    const int KT = K >> 6;                     // K-tiles of 64

    auto fill_stage = [&](int stage, long long k0) {
        uint32_t s = sb + stage * STAGE_B;
        fill_tile(s, pA, m0, lda, k0, tid);
        if (TRB) fill_tile_trb(s + TILE_B, pB, n0, ldb, k0, tid);
        else     fill_tile(s + TILE_B, pB, n0, ldb, k0, tid);
    };

    // prologue: 2 stages ahead
    #pragma unroll
    for (int s = 0; s < 2; ++s) {
        fill_stage(s, (long long)s * 64);
        cpa_commit();
    }

    for (int kt = 0; kt < KT; ++kt) {
        const int fs = kt + 2;
        if (fs < KT) fill_stage(fs % 3, (long long)fs * 64);
        cpa_commit();
        cpa_wait<2>();
        __syncthreads();

        const uint32_t st = sb + (kt % 3) * STAGE_B;
        const uint32_t aB = st;
        const uint32_t bB = st + TILE_B;

        #pragma unroll
        for (int kk = 0; kk < 4; ++kk) {
            const int cc = kk * 2 + cOff;      // 0..7
            uint32_t ah[4][4];
            #pragma unroll
            for (int im = 0; im < 4; ++im) {
                uint32_t off = (uint32_t)((wm + im * 16 + rowL) * TROW + cc * 16);
                ldm_x4(aB + off, ah[im][0], ah[im][1], ah[im][2], ah[im][3]);
            }
            uint32_t bh[4][4];
            #pragma unroll
            for (int nb = 0; nb < 4; ++nb) {
                if (TRB) {
                    uint32_t off = (uint32_t)(
                        (kk * 16 + ((lane >> 4) & 1) * 8 + (lane & 7)) * TRB_ROW +
                        (wn + nb * 16 + ((lane >> 3) & 1) * 8) * 2);
                    ldm_x4_trans(bB + off, bh[nb][0], bh[nb][1], bh[nb][2], bh[nb][3]);
                } else {
                    uint32_t off = (uint32_t)((wn + nb * 16 + rowL) * TROW + cc * 16);
                    ldm_x4(bB + off, bh[nb][0], bh[nb][1], bh[nb][2], bh[nb][3]);
                }
            }
            #pragma unroll
            for (int im = 0; im < 4; ++im) {
                #pragma unroll
                for (int j = 0; j < 8; ++j) {
                    const int nb = j >> 1, sel = j & 1;
                    mma_f16(acc[im][j], ah[im], bh[nb][sel], bh[nb][sel + 2]);
                }
            }
        }
        __syncthreads();
    }

    // ---- epilogue ----
    const int rql = lane >> 2;
    const int cql = (lane & 3) * 2;

    #pragma unroll
    for (int im = 0; im < 4; ++im) {
        #pragma unroll
        for (int j = 0; j < 8; ++j) {
            #pragma unroll
            for (int half = 0; half < 2; ++half) {
                const long long gm = m0 + wm + im * 16 + rql + half * 8;
                const long long gn = n0 + wn + j * 8 + cql;
                float v0 = acc[im][j][half * 2 + 0];
                float v1 = acc[im][j][half * 2 + 1];

                if (EPI == EPI_BIAS || EPI == EPI_BIAS_RELU || EPI == EPI_BIAS_ADDX) {
                    float2 bv = *reinterpret_cast<const float2*>(&bias[gn]);
                    v0 += bv.x; v1 += bv.y;
                }
                if (EPI == EPI_BIAS_RELU) { v0 = fmaxf(v0, 0.0f); v1 = fmaxf(v1, 0.0f); }
                if (EPI == EPI_BIAS_ADDX) {
                    float2 ev = *reinterpret_cast<const float2*>(&Exf[gm * lde + gn]);
                    v0 += ev.x; v1 += ev.y;
                }
                if (EPI == EPI_GATE) {
                    uint32_t gp = *reinterpret_cast<const uint32_t*>(&Exh[gm * lde + gn]);
                    v0 *= __half2float(__ushort_as_half((unsigned short)(gp & 0xFFFF)));
                    v1 *= __half2float(__ushort_as_half((unsigned short)(gp >> 16)));
                }
                if (EPI == EPI_RELUSQ) {
                    float r0 = fmaxf(v0 * scale, 0.0f), r1 = fmaxf(v1 * scale, 0.0f);
                    v0 = r0 * r0; v1 = r1 * r1;
                }

                const long long oi = coff + gm * ldc + gn;
                if (OUT == 0) {
                    *reinterpret_cast<float2*>(&Cf[oi]) = make_float2(v0, v1);
                } else {
                    *reinterpret_cast<uint32_t*>(&Ch[oi]) =
                        pack2(__float2half_rn(v0), __float2half_rn(v1));
                }
            }
        }
    }
}

// ----------------------------------------------------------------------------
// LayerNorm (D=512)
// ----------------------------------------------------------------------------
__device__ __forceinline__ float block_sum_512(float v, float* red)
{
    #pragma unroll
    for (int o = 16; o > 0; o >>= 1) v += __shfl_down_sync(0xffffffffu, v, o);
    if ((threadIdx.x & 31) == 0) red[threadIdx.x >> 5] = v;
    __syncthreads();
    if (threadIdx.x == 0) {
        float s = 0.0f;
        #pragma unroll
        for (int i = 0; i < 8; i++) s += red[i];
        red[0] = s;
    }
    __syncthreads();
    float r = red[0];
    __syncthreads();
    return r;
}

template<bool HALF_OUT>
__global__ void __launch_bounds__(256)
ln_kernel(const float* __restrict__ in, const float* __restrict__ g,
          const float* __restrict__ b, const float* __restrict__ resid,
          float* __restrict__ outf, __half* __restrict__ oh)
{
    __shared__ float red[8];
    const long long row = blockIdx.x;
    const int t = threadIdx.x;
    const float* rp = in + row * Dn;

    float v0 = rp[t], v1 = rp[t + 256];
    float mean = block_sum_512(v0 + v1, red) * (1.0f / Dn);
    float d0 = v0 - mean, d1 = v1 - mean;
    float var = block_sum_512(d0 * d0 + d1 * d1, red) * (1.0f / Dn);
    float inv = rsqrtf(var + LN_EPS);

    float o0 = d0 * inv * g[t]       + b[t];
    float o1 = d1 * inv * g[t + 256] + b[t + 256];
    if (HALF_OUT) {
        oh[row * Dn + t]       = __float2half_rn(o0);
        oh[row * Dn + t + 256] = __float2half_rn(o1);
    } else {
        if (resid) {
            o0 += resid[row * Dn + t];
            o1 += resid[row * Dn + t + 256];
        }
        outf[row * Dn + t]       = o0;
        outf[row * Dn + t + 256] = o1;
    }
}

// ----------------------------------------------------------------------------
// fused fp32 -> fp16 converter for x + 4 weights
// ----------------------------------------------------------------------------
constexpr int Q_X  = BSn * Dn / 4;
constexpr int Q_WM = Dn * Dn / 4;
constexpr int Q_WH = 2 * HIDn * Dn / 4;
constexpr int Q_WQ = QKDn * Dn / 4;
constexpr int Q_WO = Dn * HIDn / 4;
constexpr int Q_TOT = Q_X + Q_WM + Q_WH + Q_WQ + Q_WO;

__global__ void __launch_bounds__(256)
cvt_all_kernel(const float* __restrict__ x,  __half* xh,
               const float* __restrict__ wm, __half* wmh,
               const float* __restrict__ wh, __half* whh,
               const float* __restrict__ wq, __half* wqh,
               const float* __restrict__ wo, __half* woh)
{
    int i = blockIdx.x * 256 + threadIdx.x;
    if (i >= Q_TOT) return;
    const float* in; __half* oh;
    if (i < Q_X)                        { in = x;  oh = xh;  }
    else if ((i -= Q_X)  < Q_WM)        { in = wm; oh = wmh; }
    else if ((i -= Q_WM) < Q_WH)        { in = wh; oh = whh; }
    else if ((i -= Q_WH) < Q_WQ)        { in = wq; oh = wqh; }
    else     { i -= Q_WQ;                 in = wo; oh = woh; }

    float4 v = reinterpret_cast<const float4*>(in)[i];
    reinterpret_cast<uint2*>(oh)[i] = make_uint2(
        pack2(__float2half_rn(v.x), __float2half_rn(v.y)),
        pack2(__float2half_rn(v.z), __float2half_rn(v.w)));
}

// transpose (fp32 in, fp16 out): out[c][r] = in[r][c]   (Wb only)
__global__ void __launch_bounds__(256)
cvt_tr_kernel(const float* __restrict__ in, __half* __restrict__ oh,
              int ldin, int ldout)
{
    __shared__ float tbuf[32][33];
    const int c0 = blockIdx.x * 32, r0 = blockIdx.y * 32;
    const int tx = threadIdx.x & 31, ty = threadIdx.x >> 5;

    #pragma unroll
    for (int i = 0; i < 4; i++)
        tbuf[ty + i * 8][tx] = in[(long long)(r0 + ty + i * 8) * ldin + c0 + tx];
    __syncthreads();
    #pragma unroll
    for (int i = 0; i < 4; i++) {
        float v = tbuf[tx][ty + i * 8];
        long long oi = (long long)(c0 + ty + i * 8) * ldout + r0 + tx;
        oh[oi] = __float2half_rn(v);
    }
}

// ----------------------------------------------------------------------------
// launch  (R10 schedule)
// ----------------------------------------------------------------------------
extern "C" void kernel_launch(void* const* d_in, const int* in_sizes, int n_in,
                              void* d_out, int out_size)
{
    const float* x  = (const float*)d_in[0];
    const float* Wm = (const float*)d_in[1];
    const float* bm = (const float*)d_in[2];
    const float* g1 = (const float*)d_in[3];
    const float* b1 = (const float*)d_in[4];
    const float* Wh = (const float*)d_in[5];
    const float* bh = (const float*)d_in[6];
    const float* Wq = (const float*)d_in[7];
    const float* bq = (const float*)d_in[8];
    const float* Wb = (const float*)d_in[9];
    const float* Wo = (const float*)d_in[10];
    const float* bo = (const float*)d_in[11];
    const float* g2 = (const float*)d_in[12];
    const float* b2 = (const float*)d_in[13];
    float* out = (float*)d_out;

    __half *xh, *Wmh, *Whh, *Wqh, *Woh, *WbTh;
    __half *nh, *Zh, *ZWh, *Amh, *Vh, *hb;
    float *tmp1, *U;
    cudaGetSymbolAddress((void**)&xh, g_xh);
    cudaGetSymbolAddress((void**)&Wmh, g_Wmh);
    cudaGetSymbolAddress((void**)&Whh, g_Whh);
    cudaGetSymbolAddress((void**)&Wqh, g_Wqh);
    cudaGetSymbolAddress((void**)&Woh, g_Woh);
    cudaGetSymbolAddress((void**)&WbTh, g_WbTh);
    cudaGetSymbolAddress((void**)&nh, g_nh);
    cudaGetSymbolAddress((void**)&Zh, g_Zh);
    cudaGetSymbolAddress((void**)&ZWh, g_ZWh);
    cudaGetSymbolAddress((void**)&Amh, g_Amh);
    cudaGetSymbolAddress((void**)&Vh, g_Vh);
    cudaGetSymbolAddress((void**)&hb, g_hbuf);
    cudaGetSymbolAddress((void**)&tmp1, g_tmp1);
    cudaGetSymbolAddress((void**)&U, g_U);

    constexpr int SM1 = StageCfg<false>::SMEM;   // 110592
    constexpr int SMT = StageCfg<true>::SMEM;    // 107520
    cudaFuncSetAttribute((const void*)tgemm<EPI_BIAS_ADDX, 0>, cudaFuncAttributeMaxDynamicSharedMemorySize, SM1);
    cudaFuncSetAttribute((const void*)tgemm<EPI_BIAS_RELU, 1>, cudaFuncAttributeMaxDynamicSharedMemorySize, SM1);
    cudaFuncSetAttribute((const void*)tgemm<EPI_NONE, 1>,      cudaFuncAttributeMaxDynamicSharedMemorySize, SM1);
    cudaFuncSetAttribute((const void*)tgemm<EPI_RELUSQ, 1>,    cudaFuncAttributeMaxDynamicSharedMemorySize, SM1);
    cudaFuncSetAttribute((const void*)tgemm<EPI_GATE, 1, true>,cudaFuncAttributeMaxDynamicSharedMemorySize, SMT);
    cudaFuncSetAttribute((const void*)tgemm<EPI_BIAS, 0>,      cudaFuncAttributeMaxDynamicSharedMemorySize, SM1);

    cudaStream_t s1;
    cudaEvent_t evF, evJ;
    cudaStreamCreateWithFlags(&s1, cudaStreamNonBlocking);
    cudaEventCreateWithFlags(&evF, cudaEventDisableTiming);
    cudaEventCreateWithFlags(&evJ, cudaEventDisableTiming);

    const float inv_s = 1.0f / (float)Sn;

    // 0) conversions
    cvt_all_kernel<<<(Q_TOT + 255) / 256, 256>>>(
        x, xh, Wm, Wmh, Wh, Whh, Wq, Wqh, Wo, Woh);
    cvt_tr_kernel<<<dim3(QKDn / 32, QKDn / 32, 1), 256>>>(Wb, WbTh, QKDn, QKDn);

    // 1) tmp1 = x @ Wm^T + bm + x
    tgemm<EPI_BIAS_ADDX, 0><<<dim3(Dn / 128, BSn / 128, 1), 128, SM1>>>(
        xh, Wmh, bm, x, tmp1, nullptr,
        Dn, Dn, Dn, Dn, 0, 0, 0, 0, Dn, 1.0f);

    // 2) nrm = LN(tmp1) -> fp16
    ln_kernel<true><<<BSn, 256>>>(tmp1, g1, b1, nullptr, nullptr, nh);

    // fork: branch B (Z -> ZW -> QK) on s1, branch A (Wh) stays on default
    cudaEventRecord(evF, 0);
    cudaStreamWaitEvent(s1, evF, 0);

    // 4) Z = relu(nrm @ Wq^T + bq)   (s1)
    tgemm<EPI_BIAS_RELU, 1><<<dim3(QKDn / 128, BSn / 128, 1), 128, SM1, s1>>>(
        nh, Wqh, bq, nullptr, nullptr, Zh,
        Dn, Dn, Dn, QKDn, 0, 0, 0, 0, 0, 1.0f);

    // 5) ZW = Z @ Wb                 (s1)
    tgemm<EPI_NONE, 1><<<dim3(QKDn / 128, BSn / 128, 1), 128, SM1, s1>>>(
        Zh, WbTh, nullptr, nullptr, nullptr, ZWh,
        QKDn, QKDn, QKDn, QKDn, 0, 0, 0, 0, 0, 1.0f);

    // 6) A = relu((ZW @ Z^T)/S)^2    (s1)
    tgemm<EPI_RELUSQ, 1><<<dim3(Sn / 128, Sn / 128, Bn), 128, SM1, s1>>>(
        ZWh, Zh, nullptr, nullptr, nullptr, Amh,
        QKDn, QKDn, QKDn, Sn,
        (long long)Sn * QKDn, (long long)Sn * QKDn, (long long)Sn * Sn, 0, 0, inv_s);

    // 3) h = relu(nrm @ Wh^T + bh) -> fp16   (default stream, overlaps 4-6)
    tgemm<EPI_BIAS_RELU, 1><<<dim3(2 * HIDn / 128, BSn / 128, 1), 128, SM1>>>(
        nh, Whh, bh, nullptr, nullptr, hb,
        Dn, Dn, Dn, 2 * HIDn, 0, 0, 0, 0, 0, 1.0f);

    // join
    cudaEventRecord(evJ, s1);
    cudaStreamWaitEvent(0, evJ, 0);

    // 8) V = (A @ v) * gate   (v read in-place from hb via ldmatrix.trans)
    tgemm<EPI_GATE, 1, true><<<dim3(HIDn / 128, Sn / 128, Bn), 128, SMT>>>(
        Amh, hb, nullptr, hb + HIDn, nullptr, Vh,
        Sn, Sn, 2 * HIDn, HIDn,
        (long long)Sn * Sn, (long long)Sn * 2 * HIDn, (long long)Sn * HIDn,
        (long long)Sn * 2 * HIDn, 2 * HIDn, 1.0f);

    // 9) U = V @ Wo^T + bo
    tgemm<EPI_BIAS, 0><<<dim3(Dn / 128, BSn / 128, 1), 128, SM1>>>(
        Vh, Woh, bo, nullptr, U, nullptr,
        HIDn, HIDn, HIDn, Dn, 0, 0, 0, 0, 0, 1.0f);

    // 10) out = LN(U) + x
    ln_kernel<false><<<BSn, 256>>>(U, g2, b2, x, out, nullptr);
}

// round 15
// speedup vs baseline: 1.1637x; 1.0149x over previous
#include <cuda_runtime.h>
#include <cuda_fp16.h>
#include <cstdint>

// GAU block on GB300 (plain sm_103 target): fp16 1-pass GEMMs on
// mma.sync.m16n8k16 + ldmatrix + cp.async.
// R15 = R14 + single-barrier mainloop (wait<1>; fill after sync).
// B=4, S=2048, D=512, QKD=256, HID=1536

constexpr int Bn = 4, Sn = 2048, Dn = 512, QKDn = 256, HIDn = 1536;
constexpr int BSn = Bn * Sn;                 // 8192
constexpr float LN_EPS = 1e-5f;

// ----------------------------------------------------------------------------
// scratch (device globals)
// ----------------------------------------------------------------------------
static __device__ __align__(16) __half g_xh[BSn * Dn];
static __device__ __align__(16) __half g_Wmh[Dn * Dn];
static __device__ __align__(16) __half g_Whh[2 * HIDn * Dn];
static __device__ __align__(16) __half g_Wqh[QKDn * Dn];
static __device__ __align__(16) __half g_Woh[Dn * HIDn];
static __device__ __align__(16) __half g_WbTh[QKDn * QKDn];
static __device__ __align__(16) float  g_tmp1[BSn * Dn];
static __device__ __align__(16) __half g_nh[BSn * Dn];
static __device__ __align__(16) __half g_hbuf[BSn * 2 * HIDn];          // [v | gate]
static __device__ __align__(16) __half g_Zh[BSn * QKDn];
static __device__ __align__(16) __half g_ZWh[BSn * QKDn];
static __device__ __align__(16) __half g_Amh[(long long)Bn * Sn * Sn];
static __device__ __align__(16) __half g_Vh[BSn * HIDn];
static __device__ __align__(16) float  g_U[BSn * Dn];

// ----------------------------------------------------------------------------
// PTX helpers
// ----------------------------------------------------------------------------
__device__ __forceinline__ uint32_t smem_u32(const void* p) {
    uint32_t a;
    asm("{ .reg .u64 t; cvta.to.shared.u64 t, %1; cvt.u32.u64 %0, t; }"
        : "=r"(a) : "l"(p));
    return a;
}
__device__ __forceinline__ void cpa16(uint32_t saddr, const void* gaddr) {
    asm volatile("cp.async.cg.shared.global [%0], [%1], 16;"
                 :: "r"(saddr), "l"(gaddr) : "memory");
}
__device__ __forceinline__ void cpa_commit() {
    asm volatile("cp.async.commit_group;" ::: "memory");
}
template<int N>
__device__ __forceinline__ void cpa_wait() {
    asm volatile("cp.async.wait_group %0;" :: "n"(N) : "memory");
}
__device__ __forceinline__ void ldm_x4(uint32_t a, uint32_t& r0, uint32_t& r1,
                                       uint32_t& r2, uint32_t& r3) {
    asm volatile("ldmatrix.sync.aligned.m8n8.x4.shared.b16 {%0,%1,%2,%3}, [%4];"
                 : "=r"(r0), "=r"(r1), "=r"(r2), "=r"(r3) : "r"(a));
}
__device__ __forceinline__ void ldm_x4_trans(uint32_t a, uint32_t& r0, uint32_t& r1,
                                             uint32_t& r2, uint32_t& r3) {
    asm volatile("ldmatrix.sync.aligned.m8n8.x4.trans.shared.b16 {%0,%1,%2,%3}, [%4];"
                 : "=r"(r0), "=r"(r1), "=r"(r2), "=r"(r3) : "r"(a));
}
__device__ __forceinline__ void mma_f16(float* c, const uint32_t* a, uint32_t b0, uint32_t b1) {
    asm volatile(
        "mma.sync.aligned.m16n8k16.row.col.f32.f16.f16.f32 "
        "{%0,%1,%2,%3}, {%4,%5,%6,%7}, {%8,%9}, {%0,%1,%2,%3};"
        : "+f"(c[0]), "+f"(c[1]), "+f"(c[2]), "+f"(c[3])
        : "r"(a[0]), "r"(a[1]), "r"(a[2]), "r"(a[3]), "r"(b0), "r"(b1));
}
__device__ __forceinline__ uint32_t pack2(__half a, __half b) {
    return (uint32_t)__half_as_ushort(a) | ((uint32_t)__half_as_ushort(b) << 16);
}

// ----------------------------------------------------------------------------
// tensor GEMM (1-pass): C[m,n] = sum_k A[m,k]*B[n,k]
// A K-major. B: TRB==false -> K-major; TRB==true -> N-major (ldmatrix.trans).
// CTA tile 128x128, K-tile 64, 4 warps (2x2, 64x64 warp tiles), 3-stage pipe,
// single __syncthreads per K-iteration.
// OUT: 0 = fp32, 1 = fp16.  EPI_GATE extra fp16, EPI_BIAS_ADDX extra fp32.
// ----------------------------------------------------------------------------
enum { EPI_NONE = 0, EPI_BIAS = 1, EPI_BIAS_RELU = 2, EPI_BIAS_ADDX = 3,
       EPI_RELUSQ = 4, EPI_GATE = 5 };

constexpr int TROW = 144;                      // 128B data + 16B pad
constexpr int TILE_B = 128 * TROW;             // 18432
constexpr int TRB_ROW = 272;                   // 256B data + 16B pad
constexpr int TRB_TILE = 64 * TRB_ROW;         // 17408
template<bool TRB> struct StageCfg {
    static constexpr int STAGE_B = TILE_B + (TRB ? TRB_TILE : TILE_B);
    static constexpr int SMEM = 3 * STAGE_B;   // 110592 / 107520
};

// K-major tile: 128 rows x 128B (64 halves), padded stride 144B
__device__ __forceinline__ void fill_tile(uint32_t sbase,
                                          const __half* __restrict__ g,
                                          long long row0, int ld, long long k0, int tid)
{
    #pragma unroll
    for (int it = 0; it < 8; ++it) {
        int q = tid + it * 128;               // 1024 chunks of 16B
        int r = q >> 3, c = q & 7;
        cpa16(sbase + r * TROW + c * 16,
              g + (row0 + r) * (long long)ld + k0 + c * 8);
    }
}

// N-major tile: 64 k-rows x 256B (128 halves), padded stride 272B
__device__ __forceinline__ void fill_tile_trb(uint32_t sbase,
                                              const __half* __restrict__ g,
                                              long long n0, int ld, long long k0, int tid)
{
    #pragma unroll
    for (int it = 0; it < 8; ++it) {
        int q = tid + it * 128;               // 1024 chunks of 16B
        int r = q >> 4, c = q & 15;
        cpa16(sbase + r * TRB_ROW + c * 16,
              g + (k0 + r) * (long long)ld + n0 + c * 8);
    }
}

template<int EPI, int OUT, bool TRB = false>
__global__ void __launch_bounds__(128, 2)
tgemm(const __half* __restrict__ pA,
      const __half* __restrict__ pB,
      const float* __restrict__ bias, const void* __restrict__ extra,
      float* __restrict__ Cf, __half* __restrict__ Ch,
      int K, int lda, int ldb, int ldc,
      long long sA, long long sB, long long sC, long long sE,
      int lde, float scale)
{
    constexpr int STAGE_B = StageCfg<TRB>::STAGE_B;
    extern __shared__ char smem[];
    const int tid = threadIdx.x;
    const int wid = tid >> 5, lane = tid & 31;
    const int z = blockIdx.z;
    pA += (long long)z * sA;
    pB += (long long)z * sB;
    const float*  Exf = (EPI == EPI_BIAS_ADDX && extra)
                        ? (const float*)extra + (long long)z * sE : nullptr;
    const __half* Exh = (EPI == EPI_GATE && extra)
                        ? (const __half*)extra + (long long)z * sE : nullptr;
    const long long coff = (long long)z * sC;
    const long long m0 = (long long)blockIdx.y * 128;
    const long long n0 = (long long)blockIdx.x * 128;
    const uint32_t sb = smem_u32(smem);

    const int wm = (wid >> 1) * 64;
    const int wn = (wid & 1) * 64;
    const int rowL = (lane & 7) + ((lane >> 3) & 1) * 8;
    const int cOff = lane >> 4;

    float acc[4][8][4];
    #pragma unroll
    for (int i = 0; i < 4; ++i)
        #pragma unroll
        for (int j = 0; j < 8; ++j)
            #pragma unroll
            for (int t = 0; t < 4; ++t) acc[i][j][t] = 0.0f;

    const int KT = K >> 6;                     // K-tiles of 64

    auto fill_stage = [&](int stage, long long k0) {
        uint32_t s = sb + stage * STAGE_B;
        fill_tile(s, pA, m0, lda, k0, tid);
        if (TRB) fill_tile_trb(s + TILE_B, pB, n0, ldb, k0, tid);
        else     fill_tile(s + TILE_B, pB, n0, ldb, k0, tid);
    };

    // prologue: 2 stages ahead (one commit group per stage)
    #pragma unroll
    for (int s = 0; s < 2; ++s) {
        fill_stage(s, (long long)s * 64);
        cpa_commit();
    }

    // single-barrier mainloop: wait<1> -> sync -> fill(kt+2) -> compute(kt).
    // Invariant at top of iter kt: oldest pending group = stage kt; wait<1>
    // makes it resident. fill targets stage (kt+2)%3 = (kt-1)%3, whose readers
    // all passed the sync (they finished iter kt-1 before it).
    for (int kt = 0; kt < KT; ++kt) {
        cpa_wait<1>();
        __syncthreads();

        const int fs = kt + 2;
        if (fs < KT) fill_stage(fs % 3, (long long)fs * 64);
        cpa_commit();                          // one group per iteration

        const uint32_t st = sb + (kt % 3) * STAGE_B;
        const uint32_t aB = st;
        const uint32_t bB = st + TILE_B;

        #pragma unroll
        for (int kk = 0; kk < 4; ++kk) {
            const int cc = kk * 2 + cOff;      // 0..7
            uint32_t ah[4][4];
            #pragma unroll
            for (int im = 0; im < 4; ++im) {
                uint32_t off = (uint32_t)((wm + im * 16 + rowL) * TROW + cc * 16);
                ldm_x4(aB + off, ah[im][0], ah[im][1], ah[im][2], ah[im][3]);
            }
            uint32_t bh[4][4];
            #pragma unroll
            for (int nb = 0; nb < 4; ++nb) {
                if (TRB) {
                    uint32_t off = (uint32_t)(
                        (kk * 16 + ((lane >> 4) & 1) * 8 + (lane & 7)) * TRB_ROW +
                        (wn + nb * 16 + ((lane >> 3) & 1) * 8) * 2);
                    ldm_x4_trans(bB + off, bh[nb][0], bh[nb][1], bh[nb][2], bh[nb][3]);
                } else {
                    uint32_t off = (uint32_t)((wn + nb * 16 + rowL) * TROW + cc * 16);
                    ldm_x4(bB + off, bh[nb][0], bh[nb][1], bh[nb][2], bh[nb][3]);
                }
            }
            #pragma unroll
            for (int im = 0; im < 4; ++im) {
                #pragma unroll
                for (int j = 0; j < 8; ++j) {
                    const int nb = j >> 1, sel = j & 1;
                    mma_f16(acc[im][j], ah[im], bh[nb][sel], bh[nb][sel + 2]);
                }
            }
        }
    }

    // ---- epilogue ----
    const int rql = lane >> 2;
    const int cql = (lane & 3) * 2;

    #pragma unroll
    for (int im = 0; im < 4; ++im) {
        #pragma unroll
        for (int j = 0; j < 8; ++j) {
            #pragma unroll
            for (int half = 0; half < 2; ++half) {
                const long long gm = m0 + wm + im * 16 + rql + half * 8;
                const long long gn = n0 + wn + j * 8 + cql;
                float v0 = acc[im][j][half * 2 + 0];
                float v1 = acc[im][j][half * 2 + 1];

                if (EPI == EPI_BIAS || EPI == EPI_BIAS_RELU || EPI == EPI_BIAS_ADDX) {
                    float2 bv = *reinterpret_cast<const float2*>(&bias[gn]);
                    v0 += bv.x; v1 += bv.y;
                }
                if (EPI == EPI_BIAS_RELU) { v0 = fmaxf(v0, 0.0f); v1 = fmaxf(v1, 0.0f); }
                if (EPI == EPI_BIAS_ADDX) {
                    float2 ev = *reinterpret_cast<const float2*>(&Exf[gm * lde + gn]);
                    v0 += ev.x; v1 += ev.y;
                }
                if (EPI == EPI_GATE) {
                    uint32_t gp = *reinterpret_cast<const uint32_t*>(&Exh[gm * lde + gn]);
                    v0 *= __half2float(__ushort_as_half((unsigned short)(gp & 0xFFFF)));
                    v1 *= __half2float(__ushort_as_half((unsigned short)(gp >> 16)));
                }
                if (EPI == EPI_RELUSQ) {
                    float r0 = fmaxf(v0 * scale, 0.0f), r1 = fmaxf(v1 * scale, 0.0f);
                    v0 = r0 * r0; v1 = r1 * r1;
                }

                const long long oi = coff + gm * ldc + gn;
                if (OUT == 0) {
                    *reinterpret_cast<float2*>(&Cf[oi]) = make_float2(v0, v1);
                } else {
                    *reinterpret_cast<uint32_t*>(&Ch[oi]) =
                        pack2(__float2half_rn(v0), __float2half_rn(v1));
                }
            }
        }
    }
}

// ----------------------------------------------------------------------------
// LayerNorm (D=512)
// ----------------------------------------------------------------------------
__device__ __forceinline__ float block_sum_512(float v, float* red)
{
    #pragma unroll
    for (int o = 16; o > 0; o >>= 1) v += __shfl_down_sync(0xffffffffu, v, o);
    if ((threadIdx.x & 31) == 0) red[threadIdx.x >> 5] = v;
    __syncthreads();
    if (threadIdx.x == 0) {
        float s = 0.0f;
        #pragma unroll
        for (int i = 0; i < 8; i++) s += red[i];
        red[0] = s;
    }
    __syncthreads();
    float r = red[0];
    __syncthreads();
    return r;
}

template<bool HALF_OUT>
__global__ void __launch_bounds__(256)
ln_kernel(const float* __restrict__ in, const float* __restrict__ g,
          const float* __restrict__ b, const float* __restrict__ resid,
          float* __restrict__ outf, __half* __restrict__ oh)
{
    __shared__ float red[8];
    const long long row = blockIdx.x;
    const int t = threadIdx.x;
    const float* rp = in + row * Dn;

    float v0 = rp[t], v1 = rp[t + 256];
    float mean = block_sum_512(v0 + v1, red) * (1.0f / Dn);
    float d0 = v0 - mean, d1 = v1 - mean;
    float var = block_sum_512(d0 * d0 + d1 * d1, red) * (1.0f / Dn);
    float inv = rsqrtf(var + LN_EPS);

    float o0 = d0 * inv * g[t]       + b[t];
    float o1 = d1 * inv * g[t + 256] + b[t + 256];
    if (HALF_OUT) {
        oh[row * Dn + t]       = __float2half_rn(o0);
        oh[row * Dn + t + 256] = __float2half_rn(o1);
    } else {
        if (resid) {
            o0 += resid[row * Dn + t];
            o1 += resid[row * Dn + t + 256];
        }
        outf[row * Dn + t]       = o0;
        outf[row * Dn + t + 256] = o1;
    }
}

// ----------------------------------------------------------------------------
// fused fp32 -> fp16 converter for x + 4 weights
// ----------------------------------------------------------------------------
constexpr int Q_X  = BSn * Dn / 4;
constexpr int Q_WM = Dn * Dn / 4;
constexpr int Q_WH = 2 * HIDn * Dn / 4;
constexpr int Q_WQ = QKDn * Dn / 4;
constexpr int Q_WO = Dn * HIDn / 4;
constexpr int Q_TOT = Q_X + Q_WM + Q_WH + Q_WQ + Q_WO;

__global__ void __launch_bounds__(256)
cvt_all_kernel(const float* __restrict__ x,  __half* xh,
               const float* __restrict__ wm, __half* wmh,
               const float* __restrict__ wh, __half* whh,
               const float* __restrict__ wq, __half* wqh,
               const float* __restrict__ wo, __half* woh)
{
    int i = blockIdx.x * 256 + threadIdx.x;
    if (i >= Q_TOT) return;
    const float* in; __half* oh;
    if (i < Q_X)                        { in = x;  oh = xh;  }
    else if ((i -= Q_X)  < Q_WM)        { in = wm; oh = wmh; }
    else if ((i -= Q_WM) < Q_WH)        { in = wh; oh = whh; }
    else if ((i -= Q_WH) < Q_WQ)        { in = wq; oh = wqh; }
    else     { i -= Q_WQ;                 in = wo; oh = woh; }

    float4 v = reinterpret_cast<const float4*>(in)[i];
    reinterpret_cast<uint2*>(oh)[i] = make_uint2(
        pack2(__float2half_rn(v.x), __float2half_rn(v.y)),
        pack2(__float2half_rn(v.z), __float2half_rn(v.w)));
}

// transpose (fp32 in, fp16 out): out[c][r] = in[r][c]   (Wb only)
__global__ void __launch_bounds__(256)
cvt_tr_kernel(const float* __restrict__ in, __half* __restrict__ oh,
              int ldin, int ldout)
{
    __shared__ float tbuf[32][33];
    const int c0 = blockIdx.x * 32, r0 = blockIdx.y * 32;
    const int tx = threadIdx.x & 31, ty = threadIdx.x >> 5;

    #pragma unroll
    for (int i = 0; i < 4; i++)
        tbuf[ty + i * 8][tx] = in[(long long)(r0 + ty + i * 8) * ldin + c0 + tx];
    __syncthreads();
    #pragma unroll
    for (int i = 0; i < 4; i++) {
        float v = tbuf[tx][ty + i * 8];
        long long oi = (long long)(c0 + ty + i * 8) * ldout + r0 + tx;
        oh[oi] = __float2half_rn(v);
    }
}

// ----------------------------------------------------------------------------
// launch  (R10 schedule)
// ----------------------------------------------------------------------------
extern "C" void kernel_launch(void* const* d_in, const int* in_sizes, int n_in,
                              void* d_out, int out_size)
{
    const float* x  = (const float*)d_in[0];
    const float* Wm = (const float*)d_in[1];
    const float* bm = (const float*)d_in[2];
    const float* g1 = (const float*)d_in[3];
    const float* b1 = (const float*)d_in[4];
    const float* Wh = (const float*)d_in[5];
    const float* bh = (const float*)d_in[6];
    const float* Wq = (const float*)d_in[7];
    const float* bq = (const float*)d_in[8];
    const float* Wb = (const float*)d_in[9];
    const float* Wo = (const float*)d_in[10];
    const float* bo = (const float*)d_in[11];
    const float* g2 = (const float*)d_in[12];
    const float* b2 = (const float*)d_in[13];
    float* out = (float*)d_out;

    __half *xh, *Wmh, *Whh, *Wqh, *Woh, *WbTh;
    __half *nh, *Zh, *ZWh, *Amh, *Vh, *hb;
    float *tmp1, *U;
    cudaGetSymbolAddress((void**)&xh, g_xh);
    cudaGetSymbolAddress((void**)&Wmh, g_Wmh);
    cudaGetSymbolAddress((void**)&Whh, g_Whh);
    cudaGetSymbolAddress((void**)&Wqh, g_Wqh);
    cudaGetSymbolAddress((void**)&Woh, g_Woh);
    cudaGetSymbolAddress((void**)&WbTh, g_WbTh);
    cudaGetSymbolAddress((void**)&nh, g_nh);
    cudaGetSymbolAddress((void**)&Zh, g_Zh);
    cudaGetSymbolAddress((void**)&ZWh, g_ZWh);
    cudaGetSymbolAddress((void**)&Amh, g_Amh);
    cudaGetSymbolAddress((void**)&Vh, g_Vh);
    cudaGetSymbolAddress((void**)&hb, g_hbuf);
    cudaGetSymbolAddress((void**)&tmp1, g_tmp1);
    cudaGetSymbolAddress((void**)&U, g_U);

    constexpr int SM1 = StageCfg<false>::SMEM;   // 110592
    constexpr int SMT = StageCfg<true>::SMEM;    // 107520
    cudaFuncSetAttribute((const void*)tgemm<EPI_BIAS_ADDX, 0>, cudaFuncAttributeMaxDynamicSharedMemorySize, SM1);
    cudaFuncSetAttribute((const void*)tgemm<EPI_BIAS_RELU, 1>, cudaFuncAttributeMaxDynamicSharedMemorySize, SM1);
    cudaFuncSetAttribute((const void*)tgemm<EPI_NONE, 1>,      cudaFuncAttributeMaxDynamicSharedMemorySize, SM1);
    cudaFuncSetAttribute((const void*)tgemm<EPI_RELUSQ, 1>,    cudaFuncAttributeMaxDynamicSharedMemorySize, SM1);
    cudaFuncSetAttribute((const void*)tgemm<EPI_GATE, 1, true>,cudaFuncAttributeMaxDynamicSharedMemorySize, SMT);
    cudaFuncSetAttribute((const void*)tgemm<EPI_BIAS, 0>,      cudaFuncAttributeMaxDynamicSharedMemorySize, SM1);

    cudaStream_t s1;
    cudaEvent_t evF, evJ;
    cudaStreamCreateWithFlags(&s1, cudaStreamNonBlocking);
    cudaEventCreateWithFlags(&evF, cudaEventDisableTiming);
    cudaEventCreateWithFlags(&evJ, cudaEventDisableTiming);

    const float inv_s = 1.0f / (float)Sn;

    // 0) conversions
    cvt_all_kernel<<<(Q_TOT + 255) / 256, 256>>>(
        x, xh, Wm, Wmh, Wh, Whh, Wq, Wqh, Wo, Woh);
    cvt_tr_kernel<<<dim3(QKDn / 32, QKDn / 32, 1), 256>>>(Wb, WbTh, QKDn, QKDn);

    // 1) tmp1 = x @ Wm^T + bm + x
    tgemm<EPI_BIAS_ADDX, 0><<<dim3(Dn / 128, BSn / 128, 1), 128, SM1>>>(
        xh, Wmh, bm, x, tmp1, nullptr,
        Dn, Dn, Dn, Dn, 0, 0, 0, 0, Dn, 1.0f);

    // 2) nrm = LN(tmp1) -> fp16
    ln_kernel<true><<<BSn, 256>>>(tmp1, g1, b1, nullptr, nullptr, nh);

    // fork: branch B (Z -> ZW -> QK) on s1, branch A (Wh) stays on default
    cudaEventRecord(evF, 0);
    cudaStreamWaitEvent(s1, evF, 0);

    // 4) Z = relu(nrm @ Wq^T + bq)   (s1)
    tgemm<EPI_BIAS_RELU, 1><<<dim3(QKDn / 128, BSn / 128, 1), 128, SM1, s1>>>(
        nh, Wqh, bq, nullptr, nullptr, Zh,
        Dn, Dn, Dn, QKDn, 0, 0, 0, 0, 0, 1.0f);

    // 5) ZW = Z @ Wb                 (s1)
    tgemm<EPI_NONE, 1><<<dim3(QKDn / 128, BSn / 128, 1), 128, SM1, s1>>>(
        Zh, WbTh, nullptr, nullptr, nullptr, ZWh,
        QKDn, QKDn, QKDn, QKDn, 0, 0, 0, 0, 0, 1.0f);

    // 6) A = relu((ZW @ Z^T)/S)^2    (s1)
    tgemm<EPI_RELUSQ, 1><<<dim3(Sn / 128, Sn / 128, Bn), 128, SM1, s1>>>(
        ZWh, Zh, nullptr, nullptr, nullptr, Amh,
        QKDn, QKDn, QKDn, Sn,
        (long long)Sn * QKDn, (long long)Sn * QKDn, (long long)Sn * Sn, 0, 0, inv_s);

    // 3) h = relu(nrm @ Wh^T + bh) -> fp16   (default stream, overlaps 4-6)
    tgemm<EPI_BIAS_RELU, 1><<<dim3(2 * HIDn / 128, BSn / 128, 1), 128, SM1>>>(
        nh, Whh, bh, nullptr, nullptr, hb,
        Dn, Dn, Dn, 2 * HIDn, 0, 0, 0, 0, 0, 1.0f);

    // join
    cudaEventRecord(evJ, s1);
    cudaStreamWaitEvent(0, evJ, 0);

    // 8) V = (A @ v) * gate   (v read in-place from hb via ldmatrix.trans)
    tgemm<EPI_GATE, 1, true><<<dim3(HIDn / 128, Sn / 128, Bn), 128, SMT>>>(
        Amh, hb, nullptr, hb + HIDn, nullptr, Vh,
        Sn, Sn, 2 * HIDn, HIDn,
        (long long)Sn * Sn, (long long)Sn * 2 * HIDn, (long long)Sn * HIDn,
        (long long)Sn * 2 * HIDn, 2 * HIDn, 1.0f);

    // 9) U = V @ Wo^T + bo
    tgemm<EPI_BIAS, 0><<<dim3(Dn / 128, BSn / 128, 1), 128, SM1>>>(
        Vh, Woh, bo, nullptr, U, nullptr,
        HIDn, HIDn, HIDn, Dn, 0, 0, 0, 0, 0, 1.0f);

    // 10) out = LN(U) + x
    ln_kernel<false><<<BSn, 256>>>(U, g2, b2, x, out, nullptr);
}

// round 16
// speedup vs baseline: 1.1871x; 1.0201x over previous
#include <cuda_runtime.h>
#include <cuda_fp16.h>
#include <cstdint>

// GAU block on GB300 (plain sm_103 target): fp16 1-pass GEMMs on
// mma.sync.m16n8k16 + ldmatrix + cp.async.
// R16 = R15 + warp-per-row LayerNorm (no block barriers).
// B=4, S=2048, D=512, QKD=256, HID=1536

constexpr int Bn = 4, Sn = 2048, Dn = 512, QKDn = 256, HIDn = 1536;
constexpr int BSn = Bn * Sn;                 // 8192
constexpr float LN_EPS = 1e-5f;

// ----------------------------------------------------------------------------
// scratch (device globals)
// ----------------------------------------------------------------------------
static __device__ __align__(16) __half g_xh[BSn * Dn];
static __device__ __align__(16) __half g_Wmh[Dn * Dn];
static __device__ __align__(16) __half g_Whh[2 * HIDn * Dn];
static __device__ __align__(16) __half g_Wqh[QKDn * Dn];
static __device__ __align__(16) __half g_Woh[Dn * HIDn];
static __device__ __align__(16) __half g_WbTh[QKDn * QKDn];
static __device__ __align__(16) float  g_tmp1[BSn * Dn];
static __device__ __align__(16) __half g_nh[BSn * Dn];
static __device__ __align__(16) __half g_hbuf[BSn * 2 * HIDn];          // [v | gate]
static __device__ __align__(16) __half g_Zh[BSn * QKDn];
static __device__ __align__(16) __half g_ZWh[BSn * QKDn];
static __device__ __align__(16) __half g_Amh[(long long)Bn * Sn * Sn];
static __device__ __align__(16) __half g_Vh[BSn * HIDn];
static __device__ __align__(16) float  g_U[BSn * Dn];

// ----------------------------------------------------------------------------
// PTX helpers
// ----------------------------------------------------------------------------
__device__ __forceinline__ uint32_t smem_u32(const void* p) {
    uint32_t a;
    asm("{ .reg .u64 t; cvta.to.shared.u64 t, %1; cvt.u32.u64 %0, t; }"
        : "=r"(a) : "l"(p));
    return a;
}
__device__ __forceinline__ void cpa16(uint32_t saddr, const void* gaddr) {
    asm volatile("cp.async.cg.shared.global [%0], [%1], 16;"
                 :: "r"(saddr), "l"(gaddr) : "memory");
}
__device__ __forceinline__ void cpa_commit() {
    asm volatile("cp.async.commit_group;" ::: "memory");
}
template<int N>
__device__ __forceinline__ void cpa_wait() {
    asm volatile("cp.async.wait_group %0;" :: "n"(N) : "memory");
}
__device__ __forceinline__ void ldm_x4(uint32_t a, uint32_t& r0, uint32_t& r1,
                                       uint32_t& r2, uint32_t& r3) {
    asm volatile("ldmatrix.sync.aligned.m8n8.x4.shared.b16 {%0,%1,%2,%3}, [%4];"
                 : "=r"(r0), "=r"(r1), "=r"(r2), "=r"(r3) : "r"(a));
}
__device__ __forceinline__ void ldm_x4_trans(uint32_t a, uint32_t& r0, uint32_t& r1,
                                             uint32_t& r2, uint32_t& r3) {
    asm volatile("ldmatrix.sync.aligned.m8n8.x4.trans.shared.b16 {%0,%1,%2,%3}, [%4];"
                 : "=r"(r0), "=r"(r1), "=r"(r2), "=r"(r3) : "r"(a));
}
__device__ __forceinline__ void mma_f16(float* c, const uint32_t* a, uint32_t b0, uint32_t b1) {
    asm volatile(
        "mma.sync.aligned.m16n8k16.row.col.f32.f16.f16.f32 "
        "{%0,%1,%2,%3}, {%4,%5,%6,%7}, {%8,%9}, {%0,%1,%2,%3};"
        : "+f"(c[0]), "+f"(c[1]), "+f"(c[2]), "+f"(c[3])
        : "r"(a[0]), "r"(a[1]), "r"(a[2]), "r"(a[3]), "r"(b0), "r"(b1));
}
__device__ __forceinline__ uint32_t pack2(__half a, __half b) {
    return (uint32_t)__half_as_ushort(a) | ((uint32_t)__half_as_ushort(b) << 16);
}

// ----------------------------------------------------------------------------
// tensor GEMM (1-pass): C[m,n] = sum_k A[m,k]*B[n,k]
// A K-major. B: TRB==false -> K-major; TRB==true -> N-major (ldmatrix.trans).
// CTA tile 128x128, K-tile 64, 4 warps (2x2, 64x64 warp tiles), 3-stage pipe,
// single __syncthreads per K-iteration.
// OUT: 0 = fp32, 1 = fp16.  EPI_GATE extra fp16, EPI_BIAS_ADDX extra fp32.
// ----------------------------------------------------------------------------
enum { EPI_NONE = 0, EPI_BIAS = 1, EPI_BIAS_RELU = 2, EPI_BIAS_ADDX = 3,
       EPI_RELUSQ = 4, EPI_GATE = 5 };

constexpr int TROW = 144;                      // 128B data + 16B pad
constexpr int TILE_B = 128 * TROW;             // 18432
constexpr int TRB_ROW = 272;                   // 256B data + 16B pad
constexpr int TRB_TILE = 64 * TRB_ROW;         // 17408
template<bool TRB> struct StageCfg {
    static constexpr int STAGE_B = TILE_B + (TRB ? TRB_TILE : TILE_B);
    static constexpr int SMEM = 3 * STAGE_B;   // 110592 / 107520
};

// K-major tile: 128 rows x 128B (64 halves), padded stride 144B
__device__ __forceinline__ void fill_tile(uint32_t sbase,
                                          const __half* __restrict__ g,
                                          long long row0, int ld, long long k0, int tid)
{
    #pragma unroll
    for (int it = 0; it < 8; ++it) {
        int q = tid + it * 128;               // 1024 chunks of 16B
        int r = q >> 3, c = q & 7;
        cpa16(sbase + r * TROW + c * 16,
              g + (row0 + r) * (long long)ld + k0 + c * 8);
    }
}

// N-major tile: 64 k-rows x 256B (128 halves), padded stride 272B
__device__ __forceinline__ void fill_tile_trb(uint32_t sbase,
                                              const __half* __restrict__ g,
                                              long long n0, int ld, long long k0, int tid)
{
    #pragma unroll
    for (int it = 0; it < 8; ++it) {
        int q = tid + it * 128;               // 1024 chunks of 16B
        int r = q >> 4, c = q & 15;
        cpa16(sbase + r * TRB_ROW + c * 16,
              g + (k0 + r) * (long long)ld + n0 + c * 8);
    }
}

template<int EPI, int OUT, bool TRB = false>
__global__ void __launch_bounds__(128, 2)
tgemm(const __half* __restrict__ pA,
      const __half* __restrict__ pB,
      const float* __restrict__ bias, const void* __restrict__ extra,
      float* __restrict__ Cf, __half* __restrict__ Ch,
      int K, int lda, int ldb, int ldc,
      long long sA, long long sB, long long sC, long long sE,
      int lde, float scale)
{
    constexpr int STAGE_B = StageCfg<TRB>::STAGE_B;
    extern __shared__ char smem[];
    const int tid = threadIdx.x;
    const int wid = tid >> 5, lane = tid & 31;
    const int z = blockIdx.z;
    pA += (long long)z * sA;
    pB += (long long)z * sB;
    const float*  Exf = (EPI == EPI_BIAS_ADDX && extra)
                        ? (const float*)extra + (long long)z * sE : nullptr;
    const __half* Exh = (EPI == EPI_GATE && extra)
                        ? (const __half*)extra + (long long)z * sE : nullptr;
    const long long coff = (long long)z * sC;
    const long long m0 = (long long)blockIdx.y * 128;
    const long long n0 = (long long)blockIdx.x * 128;
    const uint32_t sb = smem_u32(smem);

    const int wm = (wid >> 1) * 64;
    const int wn = (wid & 1) * 64;
    const int rowL = (lane & 7) + ((lane >> 3) & 1) * 8;
    const int cOff = lane >> 4;

    float acc[4][8][4];
    #pragma unroll
    for (int i = 0; i < 4; ++i)
        #pragma unroll
        for (int j = 0; j < 8; ++j)
            #pragma unroll
            for (int t = 0; t < 4; ++t) acc[i][j][t] = 0.0f;

    const int KT = K >> 6;                     // K-tiles of 64

    auto fill_stage = [&](int stage, long long k0) {
        uint32_t s = sb + stage * STAGE_B;
        fill_tile(s, pA, m0, lda, k0, tid);
        if (TRB) fill_tile_trb(s + TILE_B, pB, n0, ldb, k0, tid);
        else     fill_tile(s + TILE_B, pB, n0, ldb, k0, tid);
    };

    // prologue: 2 stages ahead (one commit group per stage)
    #pragma unroll
    for (int s = 0; s < 2; ++s) {
        fill_stage(s, (long long)s * 64);
        cpa_commit();
    }

    // single-barrier mainloop: wait<1> -> sync -> fill(kt+2) -> compute(kt).
    for (int kt = 0; kt < KT; ++kt) {
        cpa_wait<1>();
        __syncthreads();

        const int fs = kt + 2;
        if (fs < KT) fill_stage(fs % 3, (long long)fs * 64);
        cpa_commit();                          // one group per iteration

        const uint32_t st = sb + (kt % 3) * STAGE_B;
        const uint32_t aB = st;
        const uint32_t bB = st + TILE_B;

        #pragma unroll
        for (int kk = 0; kk < 4; ++kk) {
            const int cc = kk * 2 + cOff;      // 0..7
            uint32_t ah[4][4];
            #pragma unroll
            for (int im = 0; im < 4; ++im) {
                uint32_t off = (uint32_t)((wm + im * 16 + rowL) * TROW + cc * 16);
                ldm_x4(aB + off, ah[im][0], ah[im][1], ah[im][2], ah[im][3]);
            }
            uint32_t bh[4][4];
            #pragma unroll
            for (int nb = 0; nb < 4; ++nb) {
                if (TRB) {
                    uint32_t off = (uint32_t)(
                        (kk * 16 + ((lane >> 4) & 1) * 8 + (lane & 7)) * TRB_ROW +
                        (wn + nb * 16 + ((lane >> 3) & 1) * 8) * 2);
                    ldm_x4_trans(bB + off, bh[nb][0], bh[nb][1], bh[nb][2], bh[nb][3]);
                } else {
                    uint32_t off = (uint32_t)((wn + nb * 16 + rowL) * TROW + cc * 16);
                    ldm_x4(bB + off, bh[nb][0], bh[nb][1], bh[nb][2], bh[nb][3]);
                }
            }
            #pragma unroll
            for (int im = 0; im < 4; ++im) {
                #pragma unroll
                for (int j = 0; j < 8; ++j) {
                    const int nb = j >> 1, sel = j & 1;
                    mma_f16(acc[im][j], ah[im], bh[nb][sel], bh[nb][sel + 2]);
                }
            }
        }
    }

    // ---- epilogue ----
    const int rql = lane >> 2;
    const int cql = (lane & 3) * 2;

    #pragma unroll
    for (int im = 0; im < 4; ++im) {
        #pragma unroll
        for (int j = 0; j < 8; ++j) {
            #pragma unroll
            for (int half = 0; half < 2; ++half) {
                const long long gm = m0 + wm + im * 16 + rql + half * 8;
                const long long gn = n0 + wn + j * 8 + cql;
                float v0 = acc[im][j][half * 2 + 0];
                float v1 = acc[im][j][half * 2 + 1];

                if (EPI == EPI_BIAS || EPI == EPI_BIAS_RELU || EPI == EPI_BIAS_ADDX) {
                    float2 bv = *reinterpret_cast<const float2*>(&bias[gn]);
                    v0 += bv.x; v1 += bv.y;
                }
                if (EPI == EPI_BIAS_RELU) { v0 = fmaxf(v0, 0.0f); v1 = fmaxf(v1, 0.0f); }
                if (EPI == EPI_BIAS_ADDX) {
                    float2 ev = *reinterpret_cast<const float2*>(&Exf[gm * lde + gn]);
                    v0 += ev.x; v1 += ev.y;
                }
                if (EPI == EPI_GATE) {
                    uint32_t gp = *reinterpret_cast<const uint32_t*>(&Exh[gm * lde + gn]);
                    v0 *= __half2float(__ushort_as_half((unsigned short)(gp & 0xFFFF)));
                    v1 *= __half2float(__ushort_as_half((unsigned short)(gp >> 16)));
                }
                if (EPI == EPI_RELUSQ) {
                    float r0 = fmaxf(v0 * scale, 0.0f), r1 = fmaxf(v1 * scale, 0.0f);
                    v0 = r0 * r0; v1 = r1 * r1;
                }

                const long long oi = coff + gm * ldc + gn;
                if (OUT == 0) {
                    *reinterpret_cast<float2*>(&Cf[oi]) = make_float2(v0, v1);
                } else {
                    *reinterpret_cast<uint32_t*>(&Ch[oi]) =
                        pack2(__float2half_rn(v0), __float2half_rn(v1));
                }
            }
        }
    }
}

// ----------------------------------------------------------------------------
// LayerNorm (D=512): warp-per-row, 8 rows per 256-thread block, no barriers.
// Lane l holds elems {l*4 + 128*i + t : i in 0..3, t in 0..3} (coalesced f4).
// ----------------------------------------------------------------------------
__device__ __forceinline__ float warp_sum(float v)
{
    #pragma unroll
    for (int o = 16; o > 0; o >>= 1) v += __shfl_xor_sync(0xffffffffu, v, o);
    return v;
}

template<bool HALF_OUT>
__global__ void __launch_bounds__(256)
ln_kernel(const float* __restrict__ in, const float* __restrict__ g,
          const float* __restrict__ b, const float* __restrict__ resid,
          float* __restrict__ outf, __half* __restrict__ oh)
{
    const int lane = threadIdx.x & 31;
    const long long row = (long long)blockIdx.x * 8 + (threadIdx.x >> 5);
    const float4* rp = reinterpret_cast<const float4*>(in + row * Dn);

    float4 v[4];
    float s = 0.0f;
    #pragma unroll
    for (int i = 0; i < 4; ++i) {
        v[i] = rp[lane + 32 * i];
        s += v[i].x + v[i].y + v[i].z + v[i].w;
    }
    const float mean = warp_sum(s) * (1.0f / Dn);

    float q = 0.0f;
    #pragma unroll
    for (int i = 0; i < 4; ++i) {
        v[i].x -= mean; v[i].y -= mean; v[i].z -= mean; v[i].w -= mean;
        q += v[i].x * v[i].x + v[i].y * v[i].y + v[i].z * v[i].z + v[i].w * v[i].w;
    }
    const float inv = rsqrtf(warp_sum(q) * (1.0f / Dn) + LN_EPS);

    #pragma unroll
    for (int i = 0; i < 4; ++i) {
        const int col = lane * 4 + 128 * i;
        float4 gv = *reinterpret_cast<const float4*>(&g[col]);
        float4 bv = *reinterpret_cast<const float4*>(&b[col]);
        float o0 = v[i].x * inv * gv.x + bv.x;
        float o1 = v[i].y * inv * gv.y + bv.y;
        float o2 = v[i].z * inv * gv.z + bv.z;
        float o3 = v[i].w * inv * gv.w + bv.w;
        if (HALF_OUT) {
            *reinterpret_cast<uint2*>(&oh[row * Dn + col]) = make_uint2(
                pack2(__float2half_rn(o0), __float2half_rn(o1)),
                pack2(__float2half_rn(o2), __float2half_rn(o3)));
        } else {
            if (resid) {
                float4 rv = *reinterpret_cast<const float4*>(&resid[row * Dn + col]);
                o0 += rv.x; o1 += rv.y; o2 += rv.z; o3 += rv.w;
            }
            *reinterpret_cast<float4*>(&outf[row * Dn + col]) =
                make_float4(o0, o1, o2, o3);
        }
    }
}

// ----------------------------------------------------------------------------
// fused fp32 -> fp16 converter for x + 4 weights
// ----------------------------------------------------------------------------
constexpr int Q_X  = BSn * Dn / 4;
constexpr int Q_WM = Dn * Dn / 4;
constexpr int Q_WH = 2 * HIDn * Dn / 4;
constexpr int Q_WQ = QKDn * Dn / 4;
constexpr int Q_WO = Dn * HIDn / 4;
constexpr int Q_TOT = Q_X + Q_WM + Q_WH + Q_WQ + Q_WO;

__global__ void __launch_bounds__(256)
cvt_all_kernel(const float* __restrict__ x,  __half* xh,
               const float* __restrict__ wm, __half* wmh,
               const float* __restrict__ wh, __half* whh,
               const float* __restrict__ wq, __half* wqh,
               const float* __restrict__ wo, __half* woh)
{
    int i = blockIdx.x * 256 + threadIdx.x;
    if (i >= Q_TOT) return;
    const float* in; __half* oh;
    if (i < Q_X)                        { in = x;  oh = xh;  }
    else if ((i -= Q_X)  < Q_WM)        { in = wm; oh = wmh; }
    else if ((i -= Q_WM) < Q_WH)        { in = wh; oh = whh; }
    else if ((i -= Q_WH) < Q_WQ)        { in = wq; oh = wqh; }
    else     { i -= Q_WQ;                 in = wo; oh = woh; }

    float4 v = reinterpret_cast<const float4*>(in)[i];
    reinterpret_cast<uint2*>(oh)[i] = make_uint2(
        pack2(__float2half_rn(v.x), __float2half_rn(v.y)),
        pack2(__float2half_rn(v.z), __float2half_rn(v.w)));
}

// transpose (fp32 in, fp16 out): out[c][r] = in[r][c]   (Wb only)
__global__ void __launch_bounds__(256)
cvt_tr_kernel(const float* __restrict__ in, __half* __restrict__ oh,
              int ldin, int ldout)
{
    __shared__ float tbuf[32][33];
    const int c0 = blockIdx.x * 32, r0 = blockIdx.y * 32;
    const int tx = threadIdx.x & 31, ty = threadIdx.x >> 5;

    #pragma unroll
    for (int i = 0; i < 4; i++)
        tbuf[ty + i * 8][tx] = in[(long long)(r0 + ty + i * 8) * ldin + c0 + tx];
    __syncthreads();
    #pragma unroll
    for (int i = 0; i < 4; i++) {
        float v = tbuf[tx][ty + i * 8];
        long long oi = (long long)(c0 + ty + i * 8) * ldout + r0 + tx;
        oh[oi] = __float2half_rn(v);
    }
}

// ----------------------------------------------------------------------------
// launch  (R10 schedule)
// ----------------------------------------------------------------------------
extern "C" void kernel_launch(void* const* d_in, const int* in_sizes, int n_in,
                              void* d_out, int out_size)
{
    const float* x  = (const float*)d_in[0];
    const float* Wm = (const float*)d_in[1];
    const float* bm = (const float*)d_in[2];
    const float* g1 = (const float*)d_in[3];
    const float* b1 = (const float*)d_in[4];
    const float* Wh = (const float*)d_in[5];
    const float* bh = (const float*)d_in[6];
    const float* Wq = (const float*)d_in[7];
    const float* bq = (const float*)d_in[8];
    const float* Wb = (const float*)d_in[9];
    const float* Wo = (const float*)d_in[10];
    const float* bo = (const float*)d_in[11];
    const float* g2 = (const float*)d_in[12];
    const float* b2 = (const float*)d_in[13];
    float* out = (float*)d_out;

    __half *xh, *Wmh, *Whh, *Wqh, *Woh, *WbTh;
    __half *nh, *Zh, *ZWh, *Amh, *Vh, *hb;
    float *tmp1, *U;
    cudaGetSymbolAddress((void**)&xh, g_xh);
    cudaGetSymbolAddress((void**)&Wmh, g_Wmh);
    cudaGetSymbolAddress((void**)&Whh, g_Whh);
    cudaGetSymbolAddress((void**)&Wqh, g_Wqh);
    cudaGetSymbolAddress((void**)&Woh, g_Woh);
    cudaGetSymbolAddress((void**)&WbTh, g_WbTh);
    cudaGetSymbolAddress((void**)&nh, g_nh);
    cudaGetSymbolAddress((void**)&Zh, g_Zh);
    cudaGetSymbolAddress((void**)&ZWh, g_ZWh);
    cudaGetSymbolAddress((void**)&Amh, g_Amh);
    cudaGetSymbolAddress((void**)&Vh, g_Vh);
    cudaGetSymbolAddress((void**)&hb, g_hbuf);
    cudaGetSymbolAddress((void**)&tmp1, g_tmp1);
    cudaGetSymbolAddress((void**)&U, g_U);

    constexpr int SM1 = StageCfg<false>::SMEM;   // 110592
    constexpr int SMT = StageCfg<true>::SMEM;    // 107520
    cudaFuncSetAttribute((const void*)tgemm<EPI_BIAS_ADDX, 0>, cudaFuncAttributeMaxDynamicSharedMemorySize, SM1);
    cudaFuncSetAttribute((const void*)tgemm<EPI_BIAS_RELU, 1>, cudaFuncAttributeMaxDynamicSharedMemorySize, SM1);
    cudaFuncSetAttribute((const void*)tgemm<EPI_NONE, 1>,      cudaFuncAttributeMaxDynamicSharedMemorySize, SM1);
    cudaFuncSetAttribute((const void*)tgemm<EPI_RELUSQ, 1>,    cudaFuncAttributeMaxDynamicSharedMemorySize, SM1);
    cudaFuncSetAttribute((const void*)tgemm<EPI_GATE, 1, true>,cudaFuncAttributeMaxDynamicSharedMemorySize, SMT);
    cudaFuncSetAttribute((const void*)tgemm<EPI_BIAS, 0>,      cudaFuncAttributeMaxDynamicSharedMemorySize, SM1);

    cudaStream_t s1;
    cudaEvent_t evF, evJ;
    cudaStreamCreateWithFlags(&s1, cudaStreamNonBlocking);
    cudaEventCreateWithFlags(&evF, cudaEventDisableTiming);
    cudaEventCreateWithFlags(&evJ, cudaEventDisableTiming);

    const float inv_s = 1.0f / (float)Sn;

    // 0) conversions
    cvt_all_kernel<<<(Q_TOT + 255) / 256, 256>>>(
        x, xh, Wm, Wmh, Wh, Whh, Wq, Wqh, Wo, Woh);
    cvt_tr_kernel<<<dim3(QKDn / 32, QKDn / 32, 1), 256>>>(Wb, WbTh, QKDn, QKDn);

    // 1) tmp1 = x @ Wm^T + bm + x
    tgemm<EPI_BIAS_ADDX, 0><<<dim3(Dn / 128, BSn / 128, 1), 128, SM1>>>(
        xh, Wmh, bm, x, tmp1, nullptr,
        Dn, Dn, Dn, Dn, 0, 0, 0, 0, Dn, 1.0f);

    // 2) nrm = LN(tmp1) -> fp16
    ln_kernel<true><<<BSn / 8, 256>>>(tmp1, g1, b1, nullptr, nullptr, nh);

    // fork: branch B (Z -> ZW -> QK) on s1, branch A (Wh) stays on default
    cudaEventRecord(evF, 0);
    cudaStreamWaitEvent(s1, evF, 0);

    // 4) Z = relu(nrm @ Wq^T + bq)   (s1)
    tgemm<EPI_BIAS_RELU, 1><<<dim3(QKDn / 128, BSn / 128, 1), 128, SM1, s1>>>(
        nh, Wqh, bq, nullptr, nullptr, Zh,
        Dn, Dn, Dn, QKDn, 0, 0, 0, 0, 0, 1.0f);

    // 5) ZW = Z @ Wb                 (s1)
    tgemm<EPI_NONE, 1><<<dim3(QKDn / 128, BSn / 128, 1), 128, SM1, s1>>>(
        Zh, WbTh, nullptr, nullptr, nullptr, ZWh,
        QKDn, QKDn, QKDn, QKDn, 0, 0, 0, 0, 0, 1.0f);

    // 6) A = relu((ZW @ Z^T)/S)^2    (s1)
    tgemm<EPI_RELUSQ, 1><<<dim3(Sn / 128, Sn / 128, Bn), 128, SM1, s1>>>(
        ZWh, Zh, nullptr, nullptr, nullptr, Amh,
        QKDn, QKDn, QKDn, Sn,
        (long long)Sn * QKDn, (long long)Sn * QKDn, (long long)Sn * Sn, 0, 0, inv_s);

    // 3) h = relu(nrm @ Wh^T + bh) -> fp16   (default stream, overlaps 4-6)
    tgemm<EPI_BIAS_RELU, 1><<<dim3(2 * HIDn / 128, BSn / 128, 1), 128, SM1>>>(
        nh, Whh, bh, nullptr, nullptr, hb,
        Dn, Dn, Dn, 2 * HIDn, 0, 0, 0, 0, 0, 1.0f);

    // join
    cudaEventRecord(evJ, s1);
    cudaStreamWaitEvent(0, evJ, 0);

    // 8) V = (A @ v) * gate   (v read in-place from hb via ldmatrix.trans)
    tgemm<EPI_GATE, 1, true><<<dim3(HIDn / 128, Sn / 128, Bn), 128, SMT>>>(
        Amh, hb, nullptr, hb + HIDn, nullptr, Vh,
        Sn, Sn, 2 * HIDn, HIDn,
        (long long)Sn * Sn, (long long)Sn * 2 * HIDn, (long long)Sn * HIDn,
        (long long)Sn * 2 * HIDn, 2 * HIDn, 1.0f);

    // 9) U = V @ Wo^T + bo
    tgemm<EPI_BIAS, 0><<<dim3(Dn / 128, BSn / 128, 1), 128, SM1>>>(
        Vh, Woh, bo, nullptr, U, nullptr,
        HIDn, HIDn, HIDn, Dn, 0, 0, 0, 0, 0, 1.0f);

    // 10) out = LN(U) + x
    ln_kernel<false><<<BSn / 8, 256>>>(U, g2, b2, x, out, nullptr);
}